// round 8
// baseline (speedup 1.0000x reference)
#include <cuda_runtime.h>
#include <cuda_fp16.h>
#include <math.h>
#include <stdint.h>

#define B_ 4
#define T_ 4096
#define D_ 1024
#define H_ 8
#define K_ 128
#define V_ 128
#define F_ 4096
#define M_ (B_*T_)   // 16384 rows

// ---------------- scratch (device globals) ----------------
__device__ __align__(128) __half g_nh[(size_t)M_*D_];
__device__ __align__(128) __half g_qh[(size_t)M_*H_*K_];
__device__ __align__(128) __half g_kh[(size_t)M_*H_*K_];
__device__ __align__(128) __half g_vh[(size_t)M_*H_*V_];
__device__ __align__(128) float g_al[(size_t)M_*H_];
__device__ __align__(128) float g_be[(size_t)M_*H_];
__device__ __align__(128) __half g_oh[(size_t)M_*H_*V_];
__device__ __align__(128) float g_x1[(size_t)M_*D_];
__device__ __align__(128) __half g_hh[(size_t)M_*D_];
__device__ __align__(128) __half g_fh[(size_t)M_*F_];
__device__ __align__(128) __half g_wq[1024*1024];
__device__ __align__(128) __half g_wk[1024*1024];
__device__ __align__(128) __half g_wv[1024*1024];
__device__ __align__(128) __half g_wo[1024*1024];
__device__ __align__(128) __half g_w1[(size_t)4096*1024];
__device__ __align__(128) __half g_w2[(size_t)1024*4096];

// ======================== PTX helpers ========================
__device__ __forceinline__ uint32_t smem_u32(const void* p) {
    uint32_t a;
    asm("{ .reg .u64 t; cvta.to.shared.u64 t, %1; cvt.u32.u64 %0, t; }" : "=r"(a) : "l"(p));
    return a;
}
__device__ __forceinline__ void cp16(uint32_t s, const void* g) {
    asm volatile("cp.async.cg.shared.global [%0], [%1], 16;\n" :: "r"(s), "l"(g));
}
__device__ __forceinline__ void cp_commit() { asm volatile("cp.async.commit_group;\n" ::: "memory"); }
template<int N> __device__ __forceinline__ void cp_wait() {
    asm volatile("cp.async.wait_group %0;\n" :: "n"(N) : "memory");
}
__device__ __forceinline__ void ldsm4(uint32_t& r0, uint32_t& r1, uint32_t& r2, uint32_t& r3, uint32_t addr) {
    asm volatile("ldmatrix.sync.aligned.m8n8.x4.shared.b16 {%0,%1,%2,%3}, [%4];"
        : "=r"(r0), "=r"(r1), "=r"(r2), "=r"(r3) : "r"(addr));
}
__device__ __forceinline__ void mma16816(float* d, const uint32_t* a, const uint32_t* b) {
    asm volatile("mma.sync.aligned.m16n8k16.row.col.f32.f16.f16.f32 "
        "{%0,%1,%2,%3},{%4,%5,%6,%7},{%8,%9},{%0,%1,%2,%3};"
        : "+f"(d[0]), "+f"(d[1]), "+f"(d[2]), "+f"(d[3])
        : "r"(a[0]), "r"(a[1]), "r"(a[2]), "r"(a[3]), "r"(b[0]), "r"(b[1]));
}
__device__ __forceinline__ float silu_f(float x) {
    return x / (1.f + __expf(-x));
}

// ======================== HMMA GEMM (R5-proven mainloop) ========================
// C[M,N] = A[M,Kd] @ W[Kd,N]; A fp16 [M,Kd]; B transposed fp16 [N,Kd].
// Tiles: 128x128x32, 8 warps (4m x 2n), warp tile 32x64, 3-stage cp.async.
// Smem rows padded to 80B -> ldmatrix conflict-free.
// EPI: 0=fp32, 1=+resid fp32, 2=+bias+GELU->fp16, 3=+bias+resid fp32,
//      4=silu+l2norm->fp16 (N tile == one head), 5=silu->fp16
#define ROWB 80
#define ARR_B (128*ROWB)             // 10240 B per array
#define STG_B (2*ARR_B)              // 20480 B per stage (A + B)
#define NSTAGE 3
#define DSMEM_SZ (NSTAGE*STG_B + 1024)

template<int EPI>
__global__ __launch_bounds__(256, 1) void tc_gemm(
    const __half* __restrict__ A, const __half* __restrict__ Bw,
    const float* __restrict__ bias, const float* __restrict__ resid,
    float* __restrict__ C, __half* __restrict__ Ch,
    int M, int N, int Kd)
{
    extern __shared__ __align__(1024) char dsm_raw[];
    const int tid = threadIdx.x;
    const int wid = tid >> 5, lane = tid & 31;
    const int row0 = blockIdx.y * 128;
    const int col0 = blockIdx.x * 128;
    const int NC = Kd >> 5;

    uint32_t sbase = smem_u32(dsm_raw);
    sbase = (sbase + 1023) & ~1023u;

    const int wm0 = (wid >> 1) * 32;
    const int wn0 = (wid & 1) * 64;

    float acc[2][8][4];
    #pragma unroll
    for (int i = 0; i < 2; i++)
        #pragma unroll
        for (int j = 0; j < 8; j++)
            #pragma unroll
            for (int r = 0; r < 4; r++) acc[i][j][r] = 0.f;

    auto load_chunk = [&](int c) {
        const int kb = c << 5;
        const uint32_t sb = sbase + (c % NSTAGE) * STG_B;
        #pragma unroll
        for (int arr = 0; arr < 2; arr++) {
            const __half* src = (arr == 0) ? A : Bw;
            const int rb = (arr == 0) ? row0 : col0;
            #pragma unroll
            for (int i2 = 0; i2 < 2; i2++) {
                int idx = tid + i2 * 256;
                int row = idx >> 2, seg = idx & 3;
                cp16(sb + arr * ARR_B + row * ROWB + seg * 16,
                     src + (size_t)(rb + row) * Kd + kb + seg * 8);
            }
        }
        cp_commit();
    };

    load_chunk(0);
    load_chunk(1);

    const int sub = lane >> 3, r8 = lane & 7;

    for (int c = 0; c < NC; c++) {
        if (c + 2 < NC) load_chunk(c + 2);
        if (c + 2 < NC) cp_wait<2>();
        else if (c + 1 < NC) cp_wait<1>();
        else cp_wait<0>();
        __syncthreads();

        const uint32_t sb = sbase + (c % NSTAGE) * STG_B;
        #pragma unroll
        for (int kk = 0; kk < 2; kk++) {
            const int kbyte = kk * 32;
            uint32_t af[2][4];
            #pragma unroll
            for (int mi = 0; mi < 2; mi++) {
                int row = wm0 + mi * 16 + (sub & 1) * 8 + r8;
                uint32_t off = row * ROWB + kbyte + (sub >> 1) * 16;
                ldsm4(af[mi][0], af[mi][1], af[mi][2], af[mi][3], sb + off);
            }
            uint32_t bf[8][2];
            #pragma unroll
            for (int nj = 0; nj < 4; nj++) {
                int row = wn0 + nj * 16 + (sub >> 1) * 8 + r8;
                uint32_t off = row * ROWB + kbyte + (sub & 1) * 16;
                ldsm4(bf[nj*2][0], bf[nj*2][1], bf[nj*2+1][0], bf[nj*2+1][1], sb + ARR_B + off);
            }
            #pragma unroll
            for (int mi = 0; mi < 2; mi++)
                #pragma unroll
                for (int ni = 0; ni < 8; ni++)
                    mma16816(acc[mi][ni], af[mi], bf[ni]);
        }
        __syncthreads();
    }

    // ---------------- epilogue ----------------
    const int bcol0 = col0 + wn0;
    if (EPI == 4) {
        // silu in place + per-row sum of squares over the full 128-col head
        float* s2buf = (float*)dsm_raw;   // [2][128]
        #pragma unroll
        for (int mi = 0; mi < 2; mi++) {
            #pragma unroll
            for (int hf = 0; hf < 2; hf++) {
                const int rowl = wm0 + mi * 16 + hf * 8 + (lane >> 2);
                float s2 = 0.f;
                #pragma unroll
                for (int ni = 0; ni < 8; ni++) {
                    float s0 = silu_f(acc[mi][ni][hf*2]);
                    float s1 = silu_f(acc[mi][ni][hf*2+1]);
                    acc[mi][ni][hf*2] = s0; acc[mi][ni][hf*2+1] = s1;
                    s2 += s0*s0 + s1*s1;
                }
                s2 += __shfl_xor_sync(~0u, s2, 1);
                s2 += __shfl_xor_sync(~0u, s2, 2);
                if ((lane & 3) == 0) s2buf[(wid & 1) * 128 + rowl] = s2;
            }
        }
        __syncthreads();
        #pragma unroll
        for (int mi = 0; mi < 2; mi++) {
            #pragma unroll
            for (int hf = 0; hf < 2; hf++) {
                const int rowl = wm0 + mi * 16 + hf * 8 + (lane >> 2);
                const int row = row0 + rowl;
                float inv = rsqrtf(s2buf[rowl] + s2buf[128 + rowl] + 1e-6f);
                #pragma unroll
                for (int ni = 0; ni < 8; ni++) {
                    const int col = bcol0 + ni * 8 + (lane & 3) * 2;
                    __half2 hh(__float2half_rn(acc[mi][ni][hf*2] * inv),
                               __float2half_rn(acc[mi][ni][hf*2+1] * inv));
                    *(uint32_t*)(Ch + (size_t)row * N + col) = *(uint32_t*)&hh;
                }
            }
        }
        return;
    }

    float2 bv[8];
    if (EPI == 2 || EPI == 3) {
        #pragma unroll
        for (int ni = 0; ni < 8; ni++)
            bv[ni] = *(const float2*)(bias + bcol0 + ni * 8 + (lane & 3) * 2);
    }
    #pragma unroll
    for (int mi = 0; mi < 2; mi++) {
        #pragma unroll
        for (int hf = 0; hf < 2; hf++) {
            const int row = row0 + wm0 + mi * 16 + hf * 8 + (lane >> 2);
            #pragma unroll
            for (int ni = 0; ni < 8; ni++) {
                const int col = bcol0 + ni * 8 + (lane & 3) * 2;
                float y0 = acc[mi][ni][hf*2];
                float y1 = acc[mi][ni][hf*2+1];
                if (EPI == 2 || EPI == 3) { y0 += bv[ni].x; y1 += bv[ni].y; }
                if (EPI == 2) {
                    y0 = 0.5f*y0*(1.f + erff(y0*0.70710678118f));
                    y1 = 0.5f*y1*(1.f + erff(y1*0.70710678118f));
                }
                if (EPI == 5) { y0 = silu_f(y0); y1 = silu_f(y1); }
                if (EPI == 1 || EPI == 3) {
                    float2 rv = *(const float2*)(resid + (size_t)row * N + col);
                    y0 += rv.x; y1 += rv.y;
                }
                if (EPI == 2 || EPI == 5) {
                    __half2 hh(__float2half_rn(y0), __float2half_rn(y1));
                    *(uint32_t*)(Ch + (size_t)row * N + col) = *(uint32_t*)&hh;
                } else {
                    *(float2*)(C + (size_t)row * N + col) = make_float2(y0, y1);
                }
            }
        }
    }
}

// ---------------- LayerNorm -> fp16 ----------------
__global__ __launch_bounds__(256) void ln_kernel(const float* __restrict__ x,
    const float* __restrict__ w, const float* __restrict__ bb,
    __half* __restrict__ oh)
{
    __shared__ float rs[8], rs2[8];
    int row = blockIdx.x, tid = threadIdx.x;
    const float4* xr = (const float4*)(x + (size_t)row * D_);
    float4 v = xr[tid];
    float s  = v.x + v.y + v.z + v.w;
    float s2 = v.x*v.x + v.y*v.y + v.z*v.z + v.w*v.w;
    #pragma unroll
    for (int m = 16; m; m >>= 1) {
        s  += __shfl_xor_sync(~0u, s,  m);
        s2 += __shfl_xor_sync(~0u, s2, m);
    }
    if ((tid & 31) == 0) { rs[tid>>5] = s; rs2[tid>>5] = s2; }
    __syncthreads();
    s = 0.f; s2 = 0.f;
    #pragma unroll
    for (int i = 0; i < 8; i++) { s += rs[i]; s2 += rs2[i]; }
    float mean = s * (1.0f/D_);
    float var  = s2 * (1.0f/D_) - mean*mean;
    float inv  = rsqrtf(var + 1e-5f);
    float4 wv = ((const float4*)w)[tid];
    float4 bv = ((const float4*)bb)[tid];
    float o0 = (v.x-mean)*inv*wv.x + bv.x;
    float o1 = (v.y-mean)*inv*wv.y + bv.y;
    float o2 = (v.z-mean)*inv*wv.z + bv.z;
    float o3 = (v.w-mean)*inv*wv.w + bv.w;
    __half2 h0(__float2half_rn(o0), __float2half_rn(o1));
    __half2 h1(__float2half_rn(o2), __float2half_rn(o3));
    ((uint2*)(oh + (size_t)row * D_))[tid] = make_uint2(*(uint32_t*)&h0, *(uint32_t*)&h1);
}

// ---------------- weight transpose: W[K,N] fp32 -> [N,K] fp16 ----------------
__global__ __launch_bounds__(256) void wconvT(const float* __restrict__ W,
    __half* __restrict__ WT, int Kd, int N)
{
    __shared__ float t[32][33];
    int n0 = blockIdx.x * 32, k0 = blockIdx.y * 32;
    int tx = threadIdx.x & 31, ty = threadIdx.x >> 5;
    #pragma unroll
    for (int i = 0; i < 4; i++)
        t[ty + 8*i][tx] = W[(size_t)(k0 + ty + 8*i) * N + n0 + tx];
    __syncthreads();
    #pragma unroll
    for (int i = 0; i < 4; i++)
        WT[(size_t)(n0 + ty + 8*i) * Kd + k0 + tx] = __float2half_rn(t[tx][ty + 8*i]);
}

// ---------------- alpha/beta: sigmoid(n @ W{a,b}) ----------------
__global__ __launch_bounds__(128) void ab_kernel(const __half* __restrict__ n,
    const float* __restrict__ Wb, const float* __restrict__ Wa,
    float* __restrict__ al, float* __restrict__ be)
{
    int row = blockIdx.x, tid = threadIdx.x;
    int g = tid >> 3, l = tid & 7;
    const float* W = (g < 8) ? Wb : Wa;
    int c = g & 7;
    const __half* nr = n + (size_t)row * D_;
    float s = 0.f;
    for (int d = l; d < D_; d += 8) s = fmaf(__half2float(nr[d]), W[d*H_ + c], s);
    s += __shfl_xor_sync(~0u, s, 1);
    s += __shfl_xor_sync(~0u, s, 2);
    s += __shfl_xor_sync(~0u, s, 4);
    if (l == 0) {
        float sig = 1.f/(1.f + __expf(-s));
        if (g < 8) be[(size_t)row*H_ + c] = sig;
        else       al[(size_t)row*H_ + c] = sig;
    }
}

// ---------------- gated delta-rule recurrence ----------------
// grid = 128 blocks ((b,h) x 4 V-splits). 256 threads: col = tid>>3 (32 cols),
// r8 = tid&7 (16 rows). fp16 in/out, fp32 state in regs, 3 smem buffers.
__global__ __launch_bounds__(256) void recur_kernel(
    const __half* __restrict__ q, const __half* __restrict__ k, const __half* __restrict__ v,
    const float* __restrict__ al, const float* __restrict__ be, __half* __restrict__ o)
{
    __shared__ __align__(16) float sk[3][160];
    __shared__ __align__(16) float sq[3][160];
    __shared__ float sv[3][32];
    __shared__ float sab[3][2];

    int blk = blockIdx.x;
    int bh = blk >> 2, split = blk & 3;
    int b = bh >> 3, h = bh & 7;
    int tid = threadIdx.x;
    int col = tid >> 3, r8 = tid & 7;
    int rbase = r8 * 20;
    int e = tid & 127;
    int sidx = (e >> 4) * 20 + (e & 15);
    size_t base  = ((size_t)b * T_ * H_ + h) * (size_t)K_;
    size_t abase = ((size_t)b * T_) * H_ + h;

    float S[16];
    #pragma unroll
    for (int i = 0; i < 16; i++) S[i] = 0.f;

    if (tid < 128) sk[0][sidx] = __half2float(k[base + e]);
    else           sq[0][sidx] = __half2float(q[base + e]);
    if (tid < 32)  sv[0][tid] = __half2float(v[base + split*32 + tid]);
    if (tid == 0) { sab[0][0] = al[abase]; sab[0][1] = be[abase]; }
    __syncthreads();

    int bufc = 0;
    for (int t = 0; t < T_; t++) {
        int bufn = bufc + 1; if (bufn == 3) bufn = 0;
        float pkq = 0.f, pv = 0.f, pa = 0.f, pb = 0.f;
        if (t + 1 < T_) {
            size_t off = base + (size_t)(t+1) * (H_*K_);
            pkq = __half2float((tid < 128) ? k[off + e] : q[off + e]);
            if (tid < 32) pv = __half2float(v[off + split*32 + tid]);
            if (tid == 0) {
                pa = al[abase + (size_t)(t+1)*H_];
                pb = be[abase + (size_t)(t+1)*H_];
            }
        }
        float kreg[16];
        float kv0 = 0.f, kv1 = 0.f, kv2 = 0.f, kv3 = 0.f;
        #pragma unroll
        for (int i4 = 0; i4 < 4; i4++) {
            float4 k4 = *(const float4*)(&sk[bufc][rbase + i4*4]);
            kreg[i4*4+0] = k4.x; kreg[i4*4+1] = k4.y;
            kreg[i4*4+2] = k4.z; kreg[i4*4+3] = k4.w;
            kv0 = fmaf(k4.x, S[i4*4+0], kv0);
            kv1 = fmaf(k4.y, S[i4*4+1], kv1);
            kv2 = fmaf(k4.z, S[i4*4+2], kv2);
            kv3 = fmaf(k4.w, S[i4*4+3], kv3);
        }
        float kv = (kv0+kv1)+(kv2+kv3);
        kv += __shfl_xor_sync(~0u, kv, 1);
        kv += __shfl_xor_sync(~0u, kv, 2);
        kv += __shfl_xor_sync(~0u, kv, 4);
        float a  = sab[bufc][0], bt = sab[bufc][1];
        float w  = bt * (sv[bufc][col] - a * kv);
        #pragma unroll
        for (int i = 0; i < 16; i++) S[i] = fmaf(a, S[i], kreg[i]*w);
        if (t + 1 < T_) {
            if (tid < 128) sk[bufn][sidx] = pkq;
            else           sq[bufn][sidx] = pkq;
            if (tid < 32)  sv[bufn][tid] = pv;
            if (tid == 0) { sab[bufn][0] = pa; sab[bufn][1] = pb; }
        }
        __syncthreads();
        float o0 = 0.f, o1 = 0.f, o2 = 0.f, o3 = 0.f;
        #pragma unroll
        for (int i4 = 0; i4 < 4; i4++) {
            float4 q4 = *(const float4*)(&sq[bufc][rbase + i4*4]);
            o0 = fmaf(q4.x, S[i4*4+0], o0);
            o1 = fmaf(q4.y, S[i4*4+1], o1);
            o2 = fmaf(q4.z, S[i4*4+2], o2);
            o3 = fmaf(q4.w, S[i4*4+3], o3);
        }
        float oa = (o0+o1)+(o2+o3);
        oa += __shfl_xor_sync(~0u, oa, 1);
        oa += __shfl_xor_sync(~0u, oa, 2);
        oa += __shfl_xor_sync(~0u, oa, 4);
        if (r8 == 0) o[base + (size_t)t*(H_*K_) + split*32 + col] = __float2half(oa);
        bufc = bufn;
    }
}

// ---------------- launch ----------------
extern "C" void kernel_launch(void* const* d_in, const int* in_sizes, int n_in,
                              void* d_out, int out_size)
{
    const float* x    = (const float*)d_in[0];
    const float* Wq   = (const float*)d_in[1];
    const float* Wk   = (const float*)d_in[2];
    const float* Wv   = (const float*)d_in[3];
    const float* Wb   = (const float*)d_in[4];
    const float* Wa   = (const float*)d_in[5];
    const float* Wo   = (const float*)d_in[6];
    const float* ln1w = (const float*)d_in[7];
    const float* ln1b = (const float*)d_in[8];
    const float* ln2w = (const float*)d_in[9];
    const float* ln2b = (const float*)d_in[10];
    const float* W1   = (const float*)d_in[11];
    const float* b1   = (const float*)d_in[12];
    const float* W2   = (const float*)d_in[13];
    const float* b2   = (const float*)d_in[14];
    float* out = (float*)d_out;

    float *al_, *be_, *x1_;
    __half *nh, *qh, *kh, *vh, *oh, *hh, *fh, *wq, *wk, *wv, *wo, *w1, *w2;
    cudaGetSymbolAddress((void**)&nh,  g_nh);
    cudaGetSymbolAddress((void**)&qh,  g_qh);
    cudaGetSymbolAddress((void**)&kh,  g_kh);
    cudaGetSymbolAddress((void**)&vh,  g_vh);
    cudaGetSymbolAddress((void**)&al_, g_al);
    cudaGetSymbolAddress((void**)&be_, g_be);
    cudaGetSymbolAddress((void**)&oh,  g_oh);
    cudaGetSymbolAddress((void**)&x1_, g_x1);
    cudaGetSymbolAddress((void**)&hh,  g_hh);
    cudaGetSymbolAddress((void**)&fh,  g_fh);
    cudaGetSymbolAddress((void**)&wq,  g_wq);
    cudaGetSymbolAddress((void**)&wk,  g_wk);
    cudaGetSymbolAddress((void**)&wv,  g_wv);
    cudaGetSymbolAddress((void**)&wo,  g_wo);
    cudaGetSymbolAddress((void**)&w1,  g_w1);
    cudaGetSymbolAddress((void**)&w2,  g_w2);

    cudaFuncSetAttribute(tc_gemm<1>, cudaFuncAttributeMaxDynamicSharedMemorySize, DSMEM_SZ);
    cudaFuncSetAttribute(tc_gemm<2>, cudaFuncAttributeMaxDynamicSharedMemorySize, DSMEM_SZ);
    cudaFuncSetAttribute(tc_gemm<3>, cudaFuncAttributeMaxDynamicSharedMemorySize, DSMEM_SZ);
    cudaFuncSetAttribute(tc_gemm<4>, cudaFuncAttributeMaxDynamicSharedMemorySize, DSMEM_SZ);
    cudaFuncSetAttribute(tc_gemm<5>, cudaFuncAttributeMaxDynamicSharedMemorySize, DSMEM_SZ);

    // launch order arranged so ncu (-s 5 -c 1) lands on the first QKV GEMM:
    // idx0: ln1, idx1-4: wconvT q/k/v/o, idx5: tc_gemm<4> (q)
    ln_kernel<<<M_, 256>>>(x, ln1w, ln1b, nh);
    wconvT<<<dim3(1024/32, 1024/32), 256>>>(Wq, wq, 1024, 1024);
    wconvT<<<dim3(1024/32, 1024/32), 256>>>(Wk, wk, 1024, 1024);
    wconvT<<<dim3(1024/32, 1024/32), 256>>>(Wv, wv, 1024, 1024);
    wconvT<<<dim3(1024/32, 1024/32), 256>>>(Wo, wo, 1024, 1024);

    dim3 g1(1024/128, M_/128);   // (8, 128)
    tc_gemm<4><<<g1, 256, DSMEM_SZ>>>(nh, wq, nullptr, nullptr, nullptr, qh, M_, 1024, 1024);
    tc_gemm<4><<<g1, 256, DSMEM_SZ>>>(nh, wk, nullptr, nullptr, nullptr, kh, M_, 1024, 1024);
    tc_gemm<5><<<g1, 256, DSMEM_SZ>>>(nh, wv, nullptr, nullptr, nullptr, vh, M_, 1024, 1024);

    ab_kernel<<<M_, 128>>>(nh, Wb, Wa, al_, be_);

    recur_kernel<<<B_*H_*4, 256>>>(qh, kh, vh, al_, be_, oh);

    tc_gemm<1><<<g1, 256, DSMEM_SZ>>>(oh, wo, nullptr, x, x1_, nullptr, M_, 1024, 1024);

    ln_kernel<<<M_, 256>>>(x1_, ln2w, ln2b, hh);

    // FFN weights converted late (only needed here)
    wconvT<<<dim3(4096/32, 1024/32), 256>>>(W1, w1, 1024, 4096);
    wconvT<<<dim3(1024/32, 4096/32), 256>>>(W2, w2, 4096, 1024);

    dim3 g2(4096/128, M_/128);   // (32, 128)
    tc_gemm<2><<<g2, 256, DSMEM_SZ>>>(hh, w1, b1, nullptr, nullptr, fh, M_, 4096, 1024);
    tc_gemm<3><<<g1, 256, DSMEM_SZ>>>(fh, w2, b2, x1_, out, nullptr, M_, 1024, 4096);
}

// round 9
// speedup vs baseline: 1.6847x; 1.6847x over previous
#include <cuda_runtime.h>
#include <cuda_fp16.h>
#include <math.h>
#include <stdint.h>

#define B_ 4
#define T_ 4096
#define D_ 1024
#define H_ 8
#define K_ 128
#define V_ 128
#define F_ 4096
#define M_ (B_*T_)   // 16384 rows

// ---------------- scratch (device globals) ----------------
__device__ __align__(128) __half g_nh[(size_t)M_*D_];
__device__ __align__(128) __half g_qh[(size_t)M_*H_*K_];
__device__ __align__(128) __half g_kh[(size_t)M_*H_*K_];
__device__ __align__(128) __half g_vh[(size_t)M_*H_*V_];
__device__ __align__(128) float g_al[(size_t)M_*H_];
__device__ __align__(128) float g_be[(size_t)M_*H_];
__device__ __align__(128) __half g_oh[(size_t)M_*H_*V_];
__device__ __align__(128) float g_x1[(size_t)M_*D_];
__device__ __align__(128) __half g_hh[(size_t)M_*D_];
__device__ __align__(128) __half g_fh[(size_t)M_*F_];
__device__ __align__(128) __half g_wq[1024*1024];
__device__ __align__(128) __half g_wk[1024*1024];
__device__ __align__(128) __half g_wv[1024*1024];
__device__ __align__(128) __half g_wo[1024*1024];
__device__ __align__(128) __half g_w1[(size_t)4096*1024];
__device__ __align__(128) __half g_w2[(size_t)1024*4096];

// ======================== PTX helpers ========================
__device__ __forceinline__ uint32_t smem_u32(const void* p) {
    uint32_t a;
    asm("{ .reg .u64 t; cvta.to.shared.u64 t, %1; cvt.u32.u64 %0, t; }" : "=r"(a) : "l"(p));
    return a;
}
__device__ __forceinline__ void cp16(uint32_t s, const void* g) {
    asm volatile("cp.async.cg.shared.global [%0], [%1], 16;\n" :: "r"(s), "l"(g));
}
__device__ __forceinline__ void cp_commit() { asm volatile("cp.async.commit_group;\n" ::: "memory"); }
template<int N> __device__ __forceinline__ void cp_wait() {
    asm volatile("cp.async.wait_group %0;\n" :: "n"(N) : "memory");
}
__device__ __forceinline__ void ldsm4(uint32_t& r0, uint32_t& r1, uint32_t& r2, uint32_t& r3, uint32_t addr) {
    asm volatile("ldmatrix.sync.aligned.m8n8.x4.shared.b16 {%0,%1,%2,%3}, [%4];"
        : "=r"(r0), "=r"(r1), "=r"(r2), "=r"(r3) : "r"(addr));
}
__device__ __forceinline__ void mma16816(float* d, const uint32_t* a, const uint32_t* b) {
    asm volatile("mma.sync.aligned.m16n8k16.row.col.f32.f16.f16.f32 "
        "{%0,%1,%2,%3},{%4,%5,%6,%7},{%8,%9},{%0,%1,%2,%3};"
        : "+f"(d[0]), "+f"(d[1]), "+f"(d[2]), "+f"(d[3])
        : "r"(a[0]), "r"(a[1]), "r"(a[2]), "r"(a[3]), "r"(b[0]), "r"(b[1]));
}
__device__ __forceinline__ float silu_f(float x) {
    return x / (1.f + __expf(-x));
}

// ======================== HMMA GEMM (R5 mainloop, 2-CTA occupancy forced) ========
// C[M,N] = A[M,Kd] @ W[Kd,N]; A fp16 [M,Kd]; B transposed fp16 [N,Kd].
// Tiles: 128x128x32, 8 warps (4m x 2n), warp tile 32x64, 3-stage cp.async.
// Smem rows padded to 80B -> ldmatrix conflict-free.
// EPI: 0=fp32, 1=+resid fp32, 2=+bias+GELU->fp16, 3=+bias+resid fp32,
//      4=silu+l2norm->fp16 (N tile == one head), 5=silu->fp16
#define ROWB 80
#define ARR_B (128*ROWB)             // 10240 B per array
#define STG_B (2*ARR_B)              // 20480 B per stage (A + B)
#define NSTAGE 3
#define DSMEM_SZ (NSTAGE*STG_B + 1024)

template<int EPI>
__global__ __launch_bounds__(256, 2) void tc_gemm(
    const __half* __restrict__ A, const __half* __restrict__ Bw,
    const float* __restrict__ bias, const float* __restrict__ resid,
    float* __restrict__ C, __half* __restrict__ Ch,
    int M, int N, int Kd)
{
    extern __shared__ __align__(1024) char dsm_raw[];
    const int tid = threadIdx.x;
    const int wid = tid >> 5, lane = tid & 31;
    const int row0 = blockIdx.y * 128;
    const int col0 = blockIdx.x * 128;
    const int NC = Kd >> 5;

    uint32_t sbase = smem_u32(dsm_raw);
    sbase = (sbase + 1023) & ~1023u;

    const int wm0 = (wid >> 1) * 32;
    const int wn0 = (wid & 1) * 64;

    float acc[2][8][4];
    #pragma unroll
    for (int i = 0; i < 2; i++)
        #pragma unroll
        for (int j = 0; j < 8; j++)
            #pragma unroll
            for (int r = 0; r < 4; r++) acc[i][j][r] = 0.f;

    auto load_chunk = [&](int c) {
        const int kb = c << 5;
        const uint32_t sb = sbase + (c % NSTAGE) * STG_B;
        #pragma unroll
        for (int arr = 0; arr < 2; arr++) {
            const __half* src = (arr == 0) ? A : Bw;
            const int rb = (arr == 0) ? row0 : col0;
            #pragma unroll
            for (int i2 = 0; i2 < 2; i2++) {
                int idx = tid + i2 * 256;
                int row = idx >> 2, seg = idx & 3;
                cp16(sb + arr * ARR_B + row * ROWB + seg * 16,
                     src + (size_t)(rb + row) * Kd + kb + seg * 8);
            }
        }
        cp_commit();
    };

    load_chunk(0);
    load_chunk(1);

    const int sub = lane >> 3, r8 = lane & 7;

    for (int c = 0; c < NC; c++) {
        if (c + 2 < NC) load_chunk(c + 2);
        if (c + 2 < NC) cp_wait<2>();
        else if (c + 1 < NC) cp_wait<1>();
        else cp_wait<0>();
        __syncthreads();

        const uint32_t sb = sbase + (c % NSTAGE) * STG_B;
        #pragma unroll
        for (int kk = 0; kk < 2; kk++) {
            const int kbyte = kk * 32;
            uint32_t af[2][4];
            #pragma unroll
            for (int mi = 0; mi < 2; mi++) {
                int row = wm0 + mi * 16 + (sub & 1) * 8 + r8;
                uint32_t off = row * ROWB + kbyte + (sub >> 1) * 16;
                ldsm4(af[mi][0], af[mi][1], af[mi][2], af[mi][3], sb + off);
            }
            uint32_t bf[8][2];
            #pragma unroll
            for (int nj = 0; nj < 4; nj++) {
                int row = wn0 + nj * 16 + (sub >> 1) * 8 + r8;
                uint32_t off = row * ROWB + kbyte + (sub & 1) * 16;
                ldsm4(bf[nj*2][0], bf[nj*2][1], bf[nj*2+1][0], bf[nj*2+1][1], sb + ARR_B + off);
            }
            #pragma unroll
            for (int mi = 0; mi < 2; mi++)
                #pragma unroll
                for (int ni = 0; ni < 8; ni++)
                    mma16816(acc[mi][ni], af[mi], bf[ni]);
        }
        __syncthreads();
    }

    // ---------------- epilogue ----------------
    const int bcol0 = col0 + wn0;
    if (EPI == 4) {
        __syncthreads();
        float* s2buf = (float*)dsm_raw;   // [2][128]
        #pragma unroll
        for (int mi = 0; mi < 2; mi++) {
            #pragma unroll
            for (int hf = 0; hf < 2; hf++) {
                const int rowl = wm0 + mi * 16 + hf * 8 + (lane >> 2);
                float s2 = 0.f;
                #pragma unroll
                for (int ni = 0; ni < 8; ni++) {
                    float s0 = silu_f(acc[mi][ni][hf*2]);
                    float s1 = silu_f(acc[mi][ni][hf*2+1]);
                    acc[mi][ni][hf*2] = s0; acc[mi][ni][hf*2+1] = s1;
                    s2 += s0*s0 + s1*s1;
                }
                s2 += __shfl_xor_sync(~0u, s2, 1);
                s2 += __shfl_xor_sync(~0u, s2, 2);
                if ((lane & 3) == 0) s2buf[(wid & 1) * 128 + rowl] = s2;
            }
        }
        __syncthreads();
        #pragma unroll
        for (int mi = 0; mi < 2; mi++) {
            #pragma unroll
            for (int hf = 0; hf < 2; hf++) {
                const int rowl = wm0 + mi * 16 + hf * 8 + (lane >> 2);
                const int row = row0 + rowl;
                float inv = rsqrtf(s2buf[rowl] + s2buf[128 + rowl] + 1e-6f);
                #pragma unroll
                for (int ni = 0; ni < 8; ni++) {
                    const int col = bcol0 + ni * 8 + (lane & 3) * 2;
                    __half2 hh(__float2half_rn(acc[mi][ni][hf*2] * inv),
                               __float2half_rn(acc[mi][ni][hf*2+1] * inv));
                    *(uint32_t*)(Ch + (size_t)row * N + col) = *(uint32_t*)&hh;
                }
            }
        }
        return;
    }

    float2 bv[8];
    if (EPI == 2 || EPI == 3) {
        #pragma unroll
        for (int ni = 0; ni < 8; ni++)
            bv[ni] = *(const float2*)(bias + bcol0 + ni * 8 + (lane & 3) * 2);
    }
    #pragma unroll
    for (int mi = 0; mi < 2; mi++) {
        #pragma unroll
        for (int hf = 0; hf < 2; hf++) {
            const int row = row0 + wm0 + mi * 16 + hf * 8 + (lane >> 2);
            #pragma unroll
            for (int ni = 0; ni < 8; ni++) {
                const int col = bcol0 + ni * 8 + (lane & 3) * 2;
                float y0 = acc[mi][ni][hf*2];
                float y1 = acc[mi][ni][hf*2+1];
                if (EPI == 2 || EPI == 3) { y0 += bv[ni].x; y1 += bv[ni].y; }
                if (EPI == 2) {
                    y0 = 0.5f*y0*(1.f + erff(y0*0.70710678118f));
                    y1 = 0.5f*y1*(1.f + erff(y1*0.70710678118f));
                }
                if (EPI == 5) { y0 = silu_f(y0); y1 = silu_f(y1); }
                if (EPI == 1 || EPI == 3) {
                    float2 rv = *(const float2*)(resid + (size_t)row * N + col);
                    y0 += rv.x; y1 += rv.y;
                }
                if (EPI == 2 || EPI == 5) {
                    __half2 hh(__float2half_rn(y0), __float2half_rn(y1));
                    *(uint32_t*)(Ch + (size_t)row * N + col) = *(uint32_t*)&hh;
                } else {
                    *(float2*)(C + (size_t)row * N + col) = make_float2(y0, y1);
                }
            }
        }
    }
}

// ---------------- LayerNorm -> fp16 ----------------
__global__ __launch_bounds__(256) void ln_kernel(const float* __restrict__ x,
    const float* __restrict__ w, const float* __restrict__ bb,
    __half* __restrict__ oh)
{
    __shared__ float rs[8], rs2[8];
    int row = blockIdx.x, tid = threadIdx.x;
    const float4* xr = (const float4*)(x + (size_t)row * D_);
    float4 v = xr[tid];
    float s  = v.x + v.y + v.z + v.w;
    float s2 = v.x*v.x + v.y*v.y + v.z*v.z + v.w*v.w;
    #pragma unroll
    for (int m = 16; m; m >>= 1) {
        s  += __shfl_xor_sync(~0u, s,  m);
        s2 += __shfl_xor_sync(~0u, s2, m);
    }
    if ((tid & 31) == 0) { rs[tid>>5] = s; rs2[tid>>5] = s2; }
    __syncthreads();
    s = 0.f; s2 = 0.f;
    #pragma unroll
    for (int i = 0; i < 8; i++) { s += rs[i]; s2 += rs2[i]; }
    float mean = s * (1.0f/D_);
    float var  = s2 * (1.0f/D_) - mean*mean;
    float inv  = rsqrtf(var + 1e-5f);
    float4 wv = ((const float4*)w)[tid];
    float4 bv = ((const float4*)bb)[tid];
    float o0 = (v.x-mean)*inv*wv.x + bv.x;
    float o1 = (v.y-mean)*inv*wv.y + bv.y;
    float o2 = (v.z-mean)*inv*wv.z + bv.z;
    float o3 = (v.w-mean)*inv*wv.w + bv.w;
    __half2 h0(__float2half_rn(o0), __float2half_rn(o1));
    __half2 h1(__float2half_rn(o2), __float2half_rn(o3));
    ((uint2*)(oh + (size_t)row * D_))[tid] = make_uint2(*(uint32_t*)&h0, *(uint32_t*)&h1);
}

// ---------------- weight transpose: W[K,N] fp32 -> [N,K] fp16 ----------------
__global__ __launch_bounds__(256) void wconvT(const float* __restrict__ W,
    __half* __restrict__ WT, int Kd, int N)
{
    __shared__ float t[32][33];
    int n0 = blockIdx.x * 32, k0 = blockIdx.y * 32;
    int tx = threadIdx.x & 31, ty = threadIdx.x >> 5;
    #pragma unroll
    for (int i = 0; i < 4; i++)
        t[ty + 8*i][tx] = W[(size_t)(k0 + ty + 8*i) * N + n0 + tx];
    __syncthreads();
    #pragma unroll
    for (int i = 0; i < 4; i++)
        WT[(size_t)(n0 + ty + 8*i) * Kd + k0 + tx] = __float2half_rn(t[tx][ty + 8*i]);
}

// ---------------- alpha/beta: sigmoid(n @ W{a,b}) ----------------
__global__ __launch_bounds__(128) void ab_kernel(const __half* __restrict__ n,
    const float* __restrict__ Wb, const float* __restrict__ Wa,
    float* __restrict__ al, float* __restrict__ be)
{
    int row = blockIdx.x, tid = threadIdx.x;
    int g = tid >> 3, l = tid & 7;
    const float* W = (g < 8) ? Wb : Wa;
    int c = g & 7;
    const __half* nr = n + (size_t)row * D_;
    float s = 0.f;
    for (int d = l; d < D_; d += 8) s = fmaf(__half2float(nr[d]), W[d*H_ + c], s);
    s += __shfl_xor_sync(~0u, s, 1);
    s += __shfl_xor_sync(~0u, s, 2);
    s += __shfl_xor_sync(~0u, s, 4);
    if (l == 0) {
        float sig = 1.f/(1.f + __expf(-s));
        if (g < 8) be[(size_t)row*H_ + c] = sig;
        else       al[(size_t)row*H_ + c] = sig;
    }
}

// ---------------- gated delta-rule recurrence ----------------
__global__ __launch_bounds__(256) void recur_kernel(
    const __half* __restrict__ q, const __half* __restrict__ k, const __half* __restrict__ v,
    const float* __restrict__ al, const float* __restrict__ be, __half* __restrict__ o)
{
    __shared__ __align__(16) float sk[3][160];
    __shared__ __align__(16) float sq[3][160];
    __shared__ float sv[3][32];
    __shared__ float sab[3][2];

    int blk = blockIdx.x;
    int bh = blk >> 2, split = blk & 3;
    int b = bh >> 3, h = bh & 7;
    int tid = threadIdx.x;
    int col = tid >> 3, r8 = tid & 7;
    int rbase = r8 * 20;
    int e = tid & 127;
    int sidx = (e >> 4) * 20 + (e & 15);
    size_t base  = ((size_t)b * T_ * H_ + h) * (size_t)K_;
    size_t abase = ((size_t)b * T_) * H_ + h;

    float S[16];
    #pragma unroll
    for (int i = 0; i < 16; i++) S[i] = 0.f;

    if (tid < 128) sk[0][sidx] = __half2float(k[base + e]);
    else           sq[0][sidx] = __half2float(q[base + e]);
    if (tid < 32)  sv[0][tid] = __half2float(v[base + split*32 + tid]);
    if (tid == 0) { sab[0][0] = al[abase]; sab[0][1] = be[abase]; }
    __syncthreads();

    int bufc = 0;
    for (int t = 0; t < T_; t++) {
        int bufn = bufc + 1; if (bufn == 3) bufn = 0;
        float pkq = 0.f, pv = 0.f, pa = 0.f, pb = 0.f;
        if (t + 1 < T_) {
            size_t off = base + (size_t)(t+1) * (H_*K_);
            pkq = __half2float((tid < 128) ? k[off + e] : q[off + e]);
            if (tid < 32) pv = __half2float(v[off + split*32 + tid]);
            if (tid == 0) {
                pa = al[abase + (size_t)(t+1)*H_];
                pb = be[abase + (size_t)(t+1)*H_];
            }
        }
        float kreg[16];
        float kv0 = 0.f, kv1 = 0.f, kv2 = 0.f, kv3 = 0.f;
        #pragma unroll
        for (int i4 = 0; i4 < 4; i4++) {
            float4 k4 = *(const float4*)(&sk[bufc][rbase + i4*4]);
            kreg[i4*4+0] = k4.x; kreg[i4*4+1] = k4.y;
            kreg[i4*4+2] = k4.z; kreg[i4*4+3] = k4.w;
            kv0 = fmaf(k4.x, S[i4*4+0], kv0);
            kv1 = fmaf(k4.y, S[i4*4+1], kv1);
            kv2 = fmaf(k4.z, S[i4*4+2], kv2);
            kv3 = fmaf(k4.w, S[i4*4+3], kv3);
        }
        float kv = (kv0+kv1)+(kv2+kv3);
        kv += __shfl_xor_sync(~0u, kv, 1);
        kv += __shfl_xor_sync(~0u, kv, 2);
        kv += __shfl_xor_sync(~0u, kv, 4);
        float a  = sab[bufc][0], bt = sab[bufc][1];
        float w  = bt * (sv[bufc][col] - a * kv);
        #pragma unroll
        for (int i = 0; i < 16; i++) S[i] = fmaf(a, S[i], kreg[i]*w);
        if (t + 1 < T_) {
            if (tid < 128) sk[bufn][sidx] = pkq;
            else           sq[bufn][sidx] = pkq;
            if (tid < 32)  sv[bufn][tid] = pv;
            if (tid == 0) { sab[bufn][0] = pa; sab[bufn][1] = pb; }
        }
        __syncthreads();
        float o0 = 0.f, o1 = 0.f, o2 = 0.f, o3 = 0.f;
        #pragma unroll
        for (int i4 = 0; i4 < 4; i4++) {
            float4 q4 = *(const float4*)(&sq[bufc][rbase + i4*4]);
            o0 = fmaf(q4.x, S[i4*4+0], o0);
            o1 = fmaf(q4.y, S[i4*4+1], o1);
            o2 = fmaf(q4.z, S[i4*4+2], o2);
            o3 = fmaf(q4.w, S[i4*4+3], o3);
        }
        float oa = (o0+o1)+(o2+o3);
        oa += __shfl_xor_sync(~0u, oa, 1);
        oa += __shfl_xor_sync(~0u, oa, 2);
        oa += __shfl_xor_sync(~0u, oa, 4);
        if (r8 == 0) o[base + (size_t)t*(H_*K_) + split*32 + col] = __float2half(oa);
        bufc = bufn;
    }
}

// ---------------- launch ----------------
extern "C" void kernel_launch(void* const* d_in, const int* in_sizes, int n_in,
                              void* d_out, int out_size)
{
    const float* x    = (const float*)d_in[0];
    const float* Wq   = (const float*)d_in[1];
    const float* Wk   = (const float*)d_in[2];
    const float* Wv   = (const float*)d_in[3];
    const float* Wb   = (const float*)d_in[4];
    const float* Wa   = (const float*)d_in[5];
    const float* Wo   = (const float*)d_in[6];
    const float* ln1w = (const float*)d_in[7];
    const float* ln1b = (const float*)d_in[8];
    const float* ln2w = (const float*)d_in[9];
    const float* ln2b = (const float*)d_in[10];
    const float* W1   = (const float*)d_in[11];
    const float* b1   = (const float*)d_in[12];
    const float* W2   = (const float*)d_in[13];
    const float* b2   = (const float*)d_in[14];
    float* out = (float*)d_out;

    float *al_, *be_, *x1_;
    __half *nh, *qh, *kh, *vh, *oh, *hh, *fh, *wq, *wk, *wv, *wo, *w1, *w2;
    cudaGetSymbolAddress((void**)&nh,  g_nh);
    cudaGetSymbolAddress((void**)&qh,  g_qh);
    cudaGetSymbolAddress((void**)&kh,  g_kh);
    cudaGetSymbolAddress((void**)&vh,  g_vh);
    cudaGetSymbolAddress((void**)&al_, g_al);
    cudaGetSymbolAddress((void**)&be_, g_be);
    cudaGetSymbolAddress((void**)&oh,  g_oh);
    cudaGetSymbolAddress((void**)&x1_, g_x1);
    cudaGetSymbolAddress((void**)&hh,  g_hh);
    cudaGetSymbolAddress((void**)&fh,  g_fh);
    cudaGetSymbolAddress((void**)&wq,  g_wq);
    cudaGetSymbolAddress((void**)&wk,  g_wk);
    cudaGetSymbolAddress((void**)&wv,  g_wv);
    cudaGetSymbolAddress((void**)&wo,  g_wo);
    cudaGetSymbolAddress((void**)&w1,  g_w1);
    cudaGetSymbolAddress((void**)&w2,  g_w2);

    cudaFuncSetAttribute(tc_gemm<1>, cudaFuncAttributeMaxDynamicSharedMemorySize, DSMEM_SZ);
    cudaFuncSetAttribute(tc_gemm<2>, cudaFuncAttributeMaxDynamicSharedMemorySize, DSMEM_SZ);
    cudaFuncSetAttribute(tc_gemm<3>, cudaFuncAttributeMaxDynamicSharedMemorySize, DSMEM_SZ);
    cudaFuncSetAttribute(tc_gemm<4>, cudaFuncAttributeMaxDynamicSharedMemorySize, DSMEM_SZ);
    cudaFuncSetAttribute(tc_gemm<5>, cudaFuncAttributeMaxDynamicSharedMemorySize, DSMEM_SZ);

    // launch order: my indices 4 AND 5 are QKV GEMMs so ncu's capture lands
    // on a GEMM regardless of whether the harness injects one leading launch.
    ln_kernel<<<M_, 256>>>(x, ln1w, ln1b, nh);                      // 0
    wconvT<<<dim3(1024/32, 1024/32), 256>>>(Wq, wq, 1024, 1024);    // 1
    wconvT<<<dim3(1024/32, 1024/32), 256>>>(Wk, wk, 1024, 1024);    // 2
    wconvT<<<dim3(1024/32, 1024/32), 256>>>(Wv, wv, 1024, 1024);    // 3

    dim3 g1(1024/128, M_/128);   // (8, 128)
    tc_gemm<4><<<g1, 256, DSMEM_SZ>>>(nh, wq, nullptr, nullptr, nullptr, qh, M_, 1024, 1024); // 4
    tc_gemm<4><<<g1, 256, DSMEM_SZ>>>(nh, wk, nullptr, nullptr, nullptr, kh, M_, 1024, 1024); // 5
    tc_gemm<5><<<g1, 256, DSMEM_SZ>>>(nh, wv, nullptr, nullptr, nullptr, vh, M_, 1024, 1024); // 6

    ab_kernel<<<M_, 128>>>(nh, Wb, Wa, al_, be_);                   // 7

    recur_kernel<<<B_*H_*4, 256>>>(qh, kh, vh, al_, be_, oh);       // 8

    wconvT<<<dim3(1024/32, 1024/32), 256>>>(Wo, wo, 1024, 1024);    // 9
    tc_gemm<1><<<g1, 256, DSMEM_SZ>>>(oh, wo, nullptr, x, x1_, nullptr, M_, 1024, 1024); // 10

    ln_kernel<<<M_, 256>>>(x1_, ln2w, ln2b, hh);                    // 11

    wconvT<<<dim3(4096/32, 1024/32), 256>>>(W1, w1, 1024, 4096);    // 12
    wconvT<<<dim3(1024/32, 4096/32), 256>>>(W2, w2, 4096, 1024);    // 13

    dim3 g2(4096/128, M_/128);   // (32, 128)
    tc_gemm<2><<<g2, 256, DSMEM_SZ>>>(hh, w1, b1, nullptr, nullptr, fh, M_, 4096, 1024); // 14
    tc_gemm<3><<<g1, 256, DSMEM_SZ>>>(fh, w2, b2, x1_, out, nullptr, M_, 1024, 4096);    // 15
}

// round 10
// speedup vs baseline: 2.0874x; 1.2391x over previous
#include <cuda_runtime.h>
#include <cuda_fp16.h>
#include <math.h>
#include <stdint.h>

#define B_ 4
#define T_ 4096
#define D_ 1024
#define H_ 8
#define K_ 128
#define V_ 128
#define F_ 4096
#define M_ (B_*T_)   // 16384 rows

// ---------------- scratch (device globals) ----------------
__device__ __align__(128) __half g_nh[(size_t)M_*D_];
__device__ __align__(128) float g_qkv[(size_t)M_*3*D_];     // combined QKV gemm out
__device__ __align__(128) float g_q [(size_t)M_*H_*K_];
__device__ __align__(128) float g_k [(size_t)M_*H_*K_];
__device__ __align__(128) float g_v [(size_t)M_*H_*V_];
__device__ __align__(128) float g_al[(size_t)M_*H_];
__device__ __align__(128) float g_be[(size_t)M_*H_];
__device__ __align__(128) float g_o [(size_t)M_*H_*V_];
__device__ __align__(128) __half g_oh[(size_t)M_*H_*V_];
__device__ __align__(128) float g_x1[(size_t)M_*D_];
__device__ __align__(128) __half g_hh[(size_t)M_*D_];
__device__ __align__(128) __half g_fh[(size_t)M_*F_];
__device__ __align__(128) __half g_wqkv[(size_t)3*1024*1024];  // [3072,1024] K-major
__device__ __align__(128) __half g_wo[1024*1024];
__device__ __align__(128) __half g_w1[(size_t)4096*1024];
__device__ __align__(128) __half g_w2[(size_t)1024*4096];

// ======================== PTX helpers ========================
__device__ __forceinline__ uint32_t smem_u32(const void* p) {
    uint32_t a;
    asm("{ .reg .u64 t; cvta.to.shared.u64 t, %1; cvt.u32.u64 %0, t; }" : "=r"(a) : "l"(p));
    return a;
}
__device__ __forceinline__ void cp16(uint32_t s, const void* g) {
    asm volatile("cp.async.cg.shared.global [%0], [%1], 16;\n" :: "r"(s), "l"(g));
}
__device__ __forceinline__ void cp_commit() { asm volatile("cp.async.commit_group;\n" ::: "memory"); }
template<int N> __device__ __forceinline__ void cp_wait() {
    asm volatile("cp.async.wait_group %0;\n" :: "n"(N) : "memory");
}
__device__ __forceinline__ void ldsm4(uint32_t& r0, uint32_t& r1, uint32_t& r2, uint32_t& r3, uint32_t addr) {
    asm volatile("ldmatrix.sync.aligned.m8n8.x4.shared.b16 {%0,%1,%2,%3}, [%4];"
        : "=r"(r0), "=r"(r1), "=r"(r2), "=r"(r3) : "r"(addr));
}
__device__ __forceinline__ void mma16816(float* d, const uint32_t* a, const uint32_t* b) {
    asm volatile("mma.sync.aligned.m16n8k16.row.col.f32.f16.f16.f32 "
        "{%0,%1,%2,%3},{%4,%5,%6,%7},{%8,%9},{%0,%1,%2,%3};"
        : "+f"(d[0]), "+f"(d[1]), "+f"(d[2]), "+f"(d[3])
        : "r"(a[0]), "r"(a[1]), "r"(a[2]), "r"(a[3]), "r"(b[0]), "r"(b[1]));
}
__device__ __forceinline__ float silu_f(float x) {
    return x / (1.f + __expf(-x));
}

// ======================== HMMA GEMM (R5-proven) ========================
// C[M,N] = A[M,Kd] @ W[Kd,N]; A fp16 [M,Kd]; B transposed fp16 [N,Kd].
// Tiles: 128x128x32, 8 warps (4m x 2n), warp tile 32x64, 3-stage cp.async.
// Smem rows padded to 80B -> ldmatrix conflict-free.
// EPI: 0=fp32, 1=+resid fp32, 2=+bias+GELU->fp16, 3=+bias+resid fp32
#define ROWB 80
#define ARR_B (128*ROWB)
#define STG_B (2*ARR_B)
#define NSTAGE 3
#define DSMEM_SZ (NSTAGE*STG_B + 1024)

template<int EPI>
__global__ __launch_bounds__(256, 2) void tc_gemm(
    const __half* __restrict__ A, const __half* __restrict__ Bw,
    const float* __restrict__ bias, const float* __restrict__ resid,
    float* __restrict__ C, __half* __restrict__ Ch,
    int M, int N, int Kd)
{
    extern __shared__ __align__(1024) char dsm_raw[];
    const int tid = threadIdx.x;
    const int wid = tid >> 5, lane = tid & 31;
    const int row0 = blockIdx.y * 128;
    const int col0 = blockIdx.x * 128;
    const int NC = Kd >> 5;

    uint32_t sbase = smem_u32(dsm_raw);
    sbase = (sbase + 1023) & ~1023u;

    const int wm0 = (wid >> 1) * 32;
    const int wn0 = (wid & 1) * 64;

    float acc[2][8][4];
    #pragma unroll
    for (int i = 0; i < 2; i++)
        #pragma unroll
        for (int j = 0; j < 8; j++)
            #pragma unroll
            for (int r = 0; r < 4; r++) acc[i][j][r] = 0.f;

    auto load_chunk = [&](int c) {
        const int kb = c << 5;
        const uint32_t sb = sbase + (c % NSTAGE) * STG_B;
        #pragma unroll
        for (int arr = 0; arr < 2; arr++) {
            const __half* src = (arr == 0) ? A : Bw;
            const int rb = (arr == 0) ? row0 : col0;
            #pragma unroll
            for (int i2 = 0; i2 < 2; i2++) {
                int idx = tid + i2 * 256;
                int row = idx >> 2, seg = idx & 3;
                cp16(sb + arr * ARR_B + row * ROWB + seg * 16,
                     src + (size_t)(rb + row) * Kd + kb + seg * 8);
            }
        }
        cp_commit();
    };

    load_chunk(0);
    load_chunk(1);

    const int sub = lane >> 3, r8 = lane & 7;

    for (int c = 0; c < NC; c++) {
        if (c + 2 < NC) load_chunk(c + 2);
        if (c + 2 < NC) cp_wait<2>();
        else if (c + 1 < NC) cp_wait<1>();
        else cp_wait<0>();
        __syncthreads();

        const uint32_t sb = sbase + (c % NSTAGE) * STG_B;
        #pragma unroll
        for (int kk = 0; kk < 2; kk++) {
            const int kbyte = kk * 32;
            uint32_t af[2][4];
            #pragma unroll
            for (int mi = 0; mi < 2; mi++) {
                int row = wm0 + mi * 16 + (sub & 1) * 8 + r8;
                uint32_t off = row * ROWB + kbyte + (sub >> 1) * 16;
                ldsm4(af[mi][0], af[mi][1], af[mi][2], af[mi][3], sb + off);
            }
            uint32_t bf[8][2];
            #pragma unroll
            for (int nj = 0; nj < 4; nj++) {
                int row = wn0 + nj * 16 + (sub >> 1) * 8 + r8;
                uint32_t off = row * ROWB + kbyte + (sub & 1) * 16;
                ldsm4(bf[nj*2][0], bf[nj*2][1], bf[nj*2+1][0], bf[nj*2+1][1], sb + ARR_B + off);
            }
            #pragma unroll
            for (int mi = 0; mi < 2; mi++)
                #pragma unroll
                for (int ni = 0; ni < 8; ni++)
                    mma16816(acc[mi][ni], af[mi], bf[ni]);
        }
        __syncthreads();
    }

    // ---------------- epilogue ----------------
    const int bcol0 = col0 + wn0;
    float2 bv[8];
    if (EPI == 2 || EPI == 3) {
        #pragma unroll
        for (int ni = 0; ni < 8; ni++)
            bv[ni] = *(const float2*)(bias + bcol0 + ni * 8 + (lane & 3) * 2);
    }
    #pragma unroll
    for (int mi = 0; mi < 2; mi++) {
        #pragma unroll
        for (int hf = 0; hf < 2; hf++) {
            const int row = row0 + wm0 + mi * 16 + hf * 8 + (lane >> 2);
            #pragma unroll
            for (int ni = 0; ni < 8; ni++) {
                const int col = bcol0 + ni * 8 + (lane & 3) * 2;
                float y0 = acc[mi][ni][hf*2];
                float y1 = acc[mi][ni][hf*2+1];
                if (EPI == 2 || EPI == 3) { y0 += bv[ni].x; y1 += bv[ni].y; }
                if (EPI == 2) {
                    y0 = 0.5f*y0*(1.f + erff(y0*0.70710678118f));
                    y1 = 0.5f*y1*(1.f + erff(y1*0.70710678118f));
                }
                if (EPI == 1 || EPI == 3) {
                    float2 rv = *(const float2*)(resid + (size_t)row * N + col);
                    y0 += rv.x; y1 += rv.y;
                }
                if (EPI == 2) {
                    __half2 hh(__float2half_rn(y0), __float2half_rn(y1));
                    *(uint32_t*)(Ch + (size_t)row * N + col) = *(uint32_t*)&hh;
                } else {
                    *(float2*)(C + (size_t)row * N + col) = make_float2(y0, y1);
                }
            }
        }
    }
}

// ---------------- LayerNorm -> fp16 ----------------
__global__ __launch_bounds__(256) void ln_kernel(const float* __restrict__ x,
    const float* __restrict__ w, const float* __restrict__ bb,
    __half* __restrict__ oh)
{
    __shared__ float rs[8], rs2[8];
    int row = blockIdx.x, tid = threadIdx.x;
    const float4* xr = (const float4*)(x + (size_t)row * D_);
    float4 v = xr[tid];
    float s  = v.x + v.y + v.z + v.w;
    float s2 = v.x*v.x + v.y*v.y + v.z*v.z + v.w*v.w;
    #pragma unroll
    for (int m = 16; m; m >>= 1) {
        s  += __shfl_xor_sync(~0u, s,  m);
        s2 += __shfl_xor_sync(~0u, s2, m);
    }
    if ((tid & 31) == 0) { rs[tid>>5] = s; rs2[tid>>5] = s2; }
    __syncthreads();
    s = 0.f; s2 = 0.f;
    #pragma unroll
    for (int i = 0; i < 8; i++) { s += rs[i]; s2 += rs2[i]; }
    float mean = s * (1.0f/D_);
    float var  = s2 * (1.0f/D_) - mean*mean;
    float inv  = rsqrtf(var + 1e-5f);
    float4 wv = ((const float4*)w)[tid];
    float4 bv = ((const float4*)bb)[tid];
    float o0 = (v.x-mean)*inv*wv.x + bv.x;
    float o1 = (v.y-mean)*inv*wv.y + bv.y;
    float o2 = (v.z-mean)*inv*wv.z + bv.z;
    float o3 = (v.w-mean)*inv*wv.w + bv.w;
    __half2 h0(__float2half_rn(o0), __float2half_rn(o1));
    __half2 h1(__float2half_rn(o2), __float2half_rn(o3));
    ((uint2*)(oh + (size_t)row * D_))[tid] = make_uint2(*(uint32_t*)&h0, *(uint32_t*)&h1);
}

// ---------------- weight transpose: W[K,N] fp32 -> [N,K] fp16 ----------------
__global__ __launch_bounds__(256) void wconvT(const float* __restrict__ W,
    __half* __restrict__ WT, int Kd, int N)
{
    __shared__ float t[32][33];
    int n0 = blockIdx.x * 32, k0 = blockIdx.y * 32;
    int tx = threadIdx.x & 31, ty = threadIdx.x >> 5;
    #pragma unroll
    for (int i = 0; i < 4; i++)
        t[ty + 8*i][tx] = W[(size_t)(k0 + ty + 8*i) * N + n0 + tx];
    __syncthreads();
    #pragma unroll
    for (int i = 0; i < 4; i++)
        WT[(size_t)(n0 + ty + 8*i) * Kd + k0 + tx] = __float2half_rn(t[tx][ty + 8*i]);
}

// ---------------- combined QKV weight transpose (one launch) ----------------
__global__ __launch_bounds__(256) void wconvT3(const float* __restrict__ Wq,
    const float* __restrict__ Wk, const float* __restrict__ Wv,
    __half* __restrict__ WT)   // [3072, 1024]
{
    __shared__ float t[32][33];
    const float* W = (blockIdx.z == 0) ? Wq : (blockIdx.z == 1) ? Wk : Wv;
    __half* dst = WT + (size_t)blockIdx.z * 1024 * 1024;
    int n0 = blockIdx.x * 32, k0 = blockIdx.y * 32;
    int tx = threadIdx.x & 31, ty = threadIdx.x >> 5;
    #pragma unroll
    for (int i = 0; i < 4; i++)
        t[ty + 8*i][tx] = W[(size_t)(k0 + ty + 8*i) * 1024 + n0 + tx];
    __syncthreads();
    #pragma unroll
    for (int i = 0; i < 4; i++)
        dst[(size_t)(n0 + ty + 8*i) * 1024 + k0 + tx] = __float2half_rn(t[tx][ty + 8*i]);
}

// ---------------- alpha/beta: sigmoid(n @ W{a,b}) ----------------
__global__ __launch_bounds__(128) void ab_kernel(const __half* __restrict__ n,
    const float* __restrict__ Wb, const float* __restrict__ Wa,
    float* __restrict__ al, float* __restrict__ be)
{
    int row = blockIdx.x, tid = threadIdx.x;
    int g = tid >> 3, l = tid & 7;
    const float* W = (g < 8) ? Wb : Wa;
    int c = g & 7;
    const __half* nr = n + (size_t)row * D_;
    float s = 0.f;
    for (int d = l; d < D_; d += 8) s = fmaf(__half2float(nr[d]), W[d*H_ + c], s);
    s += __shfl_xor_sync(~0u, s, 1);
    s += __shfl_xor_sync(~0u, s, 2);
    s += __shfl_xor_sync(~0u, s, 4);
    if (l == 0) {
        float sig = 1.f/(1.f + __expf(-s));
        if (g < 8) be[(size_t)row*H_ + c] = sig;
        else       al[(size_t)row*H_ + c] = sig;
    }
}

// ---------------- silu + l2norm on q,k; silu on v (from combined buffer) -------
__global__ __launch_bounds__(128) void act_qkv_kernel(const float* __restrict__ qkv,
    float* __restrict__ q, float* __restrict__ kk, float* __restrict__ v)
{
    __shared__ float rq[4], rk[4];
    int row = blockIdx.x, tid = threadIdx.x;     // row = m*H + h
    int m = row >> 3, h = row & 7;
    const float* src = qkv + (size_t)m * 3072 + h * 128;
    float xq = src[tid], xk = src[1024 + tid], xv = src[2048 + tid];
    float yq = silu_f(xq);
    float yk = silu_f(xk);
    float sq = yq*yq, sk2 = yk*yk;
    #pragma unroll
    for (int mm = 16; mm; mm >>= 1) {
        sq  += __shfl_xor_sync(~0u, sq,  mm);
        sk2 += __shfl_xor_sync(~0u, sk2, mm);
    }
    if ((tid & 31) == 0) { rq[tid>>5] = sq; rk[tid>>5] = sk2; }
    __syncthreads();
    float nq = rq[0]+rq[1]+rq[2]+rq[3];
    float nk = rk[0]+rk[1]+rk[2]+rk[3];
    size_t idx = (size_t)row*128 + tid;
    q[idx]  = yq * rsqrtf(nq + 1e-6f);
    kk[idx] = yk * rsqrtf(nk + 1e-6f);
    v[idx]  = silu_f(xv);
}

// ---------------- elementwise fp32 -> fp16 ----------------
__global__ __launch_bounds__(256) void conv_kernel(const float* __restrict__ x,
    __half* __restrict__ h, int n4)
{
    int i = blockIdx.x * 256 + threadIdx.x;
    if (i >= n4) return;
    float4 v = ((const float4*)x)[i];
    __half2 h0(__float2half_rn(v.x), __float2half_rn(v.y));
    __half2 h1(__float2half_rn(v.z), __float2half_rn(v.w));
    ((uint2*)h)[i] = make_uint2(*(uint32_t*)&h0, *(uint32_t*)&h1);
}

// ---------------- gated delta-rule recurrence (R5-proven, fp32, 128 thr) -------
__global__ __launch_bounds__(128) void recur_kernel(
    const float* __restrict__ q, const float* __restrict__ k, const float* __restrict__ v,
    const float* __restrict__ al, const float* __restrict__ be, float* __restrict__ o)
{
    __shared__ __align__(16) float sk[2][152];
    __shared__ __align__(16) float sq[2][152];
    __shared__ float sv[2][32];
    __shared__ float sab[2][2];

    int blk = blockIdx.x;
    int bh = blk >> 2, split = blk & 3;
    int b = bh >> 3, h = bh & 7;
    int tid = threadIdx.x;
    int col = tid >> 2, r4 = tid & 3;
    int skewIdx = ((tid >> 5) * 36) + (tid & 31);
    int rbase = r4 * 36;
    size_t base  = ((size_t)b * T_ * H_ + h) * (size_t)K_;
    size_t abase = ((size_t)b * T_) * H_ + h;

    float S[32];
    #pragma unroll
    for (int i = 0; i < 32; i++) S[i] = 0.f;

    sk[0][skewIdx] = k[base + tid];
    sq[0][skewIdx] = q[base + tid];
    if (tid < 32) sv[0][tid] = v[base + split*32 + tid];
    if (tid == 0) { sab[0][0] = al[abase]; sab[0][1] = be[abase]; }
    __syncthreads();

    int buf = 0;
    for (int t = 0; t < T_; t++) {
        float pk = 0.f, pq = 0.f, pv = 0.f, pa = 0.f, pb = 0.f;
        if (t + 1 < T_) {
            size_t off = base + (size_t)(t+1) * (H_*K_);
            pk = k[off + tid];
            pq = q[off + tid];
            if (tid < 32) pv = v[off + split*32 + tid];
            if (tid == 0) {
                pa = al[abase + (size_t)(t+1)*H_];
                pb = be[abase + (size_t)(t+1)*H_];
            }
        }
        float kreg[32];
        float kv0=0.f,kv1=0.f,kv2=0.f,kv3=0.f;
        #pragma unroll
        for (int i4 = 0; i4 < 8; i4++) {
            float4 k4 = *(const float4*)(&sk[buf][rbase + i4*4]);
            kreg[i4*4+0]=k4.x; kreg[i4*4+1]=k4.y; kreg[i4*4+2]=k4.z; kreg[i4*4+3]=k4.w;
            kv0 = fmaf(k4.x, S[i4*4+0], kv0);
            kv1 = fmaf(k4.y, S[i4*4+1], kv1);
            kv2 = fmaf(k4.z, S[i4*4+2], kv2);
            kv3 = fmaf(k4.w, S[i4*4+3], kv3);
        }
        float kv = (kv0+kv1)+(kv2+kv3);
        kv += __shfl_xor_sync(~0u, kv, 1);
        kv += __shfl_xor_sync(~0u, kv, 2);
        float a  = sab[buf][0], bt = sab[buf][1];
        float w  = bt * (sv[buf][col] - a * kv);
        #pragma unroll
        for (int i = 0; i < 32; i++) S[i] = fmaf(a, S[i], kreg[i]*w);
        float o0=0.f,o1=0.f,o2=0.f,o3=0.f;
        #pragma unroll
        for (int i4 = 0; i4 < 8; i4++) {
            float4 q4 = *(const float4*)(&sq[buf][rbase + i4*4]);
            o0 = fmaf(q4.x, S[i4*4+0], o0);
            o1 = fmaf(q4.y, S[i4*4+1], o1);
            o2 = fmaf(q4.z, S[i4*4+2], o2);
            o3 = fmaf(q4.w, S[i4*4+3], o3);
        }
        float oa = (o0+o1)+(o2+o3);
        oa += __shfl_xor_sync(~0u, oa, 1);
        oa += __shfl_xor_sync(~0u, oa, 2);
        if (r4 == 0) o[base + (size_t)t*(H_*K_) + split*32 + col] = oa;
        int nb = buf ^ 1;
        if (t + 1 < T_) {
            sk[nb][skewIdx] = pk;
            sq[nb][skewIdx] = pq;
            if (tid < 32) sv[nb][tid] = pv;
            if (tid == 0) { sab[nb][0] = pa; sab[nb][1] = pb; }
        }
        __syncthreads();
        buf = nb;
    }
}

// ---------------- launch ----------------
extern "C" void kernel_launch(void* const* d_in, const int* in_sizes, int n_in,
                              void* d_out, int out_size)
{
    const float* x    = (const float*)d_in[0];
    const float* Wq   = (const float*)d_in[1];
    const float* Wk   = (const float*)d_in[2];
    const float* Wv   = (const float*)d_in[3];
    const float* Wb   = (const float*)d_in[4];
    const float* Wa   = (const float*)d_in[5];
    const float* Wo   = (const float*)d_in[6];
    const float* ln1w = (const float*)d_in[7];
    const float* ln1b = (const float*)d_in[8];
    const float* ln2w = (const float*)d_in[9];
    const float* ln2b = (const float*)d_in[10];
    const float* W1   = (const float*)d_in[11];
    const float* b1   = (const float*)d_in[12];
    const float* W2   = (const float*)d_in[13];
    const float* b2   = (const float*)d_in[14];
    float* out = (float*)d_out;

    float *qkv_, *q_, *k_, *v_, *al_, *be_, *o_, *x1_;
    __half *nh, *oh, *hh, *fh, *wqkv, *wo, *w1, *w2;
    cudaGetSymbolAddress((void**)&nh,   g_nh);
    cudaGetSymbolAddress((void**)&qkv_, g_qkv);
    cudaGetSymbolAddress((void**)&q_,   g_q);
    cudaGetSymbolAddress((void**)&k_,   g_k);
    cudaGetSymbolAddress((void**)&v_,   g_v);
    cudaGetSymbolAddress((void**)&al_,  g_al);
    cudaGetSymbolAddress((void**)&be_,  g_be);
    cudaGetSymbolAddress((void**)&o_,   g_o);
    cudaGetSymbolAddress((void**)&oh,   g_oh);
    cudaGetSymbolAddress((void**)&x1_,  g_x1);
    cudaGetSymbolAddress((void**)&hh,   g_hh);
    cudaGetSymbolAddress((void**)&fh,   g_fh);
    cudaGetSymbolAddress((void**)&wqkv, g_wqkv);
    cudaGetSymbolAddress((void**)&wo,   g_wo);
    cudaGetSymbolAddress((void**)&w1,   g_w1);
    cudaGetSymbolAddress((void**)&w2,   g_w2);

    cudaFuncSetAttribute(tc_gemm<0>, cudaFuncAttributeMaxDynamicSharedMemorySize, DSMEM_SZ);
    cudaFuncSetAttribute(tc_gemm<1>, cudaFuncAttributeMaxDynamicSharedMemorySize, DSMEM_SZ);
    cudaFuncSetAttribute(tc_gemm<2>, cudaFuncAttributeMaxDynamicSharedMemorySize, DSMEM_SZ);
    cudaFuncSetAttribute(tc_gemm<3>, cudaFuncAttributeMaxDynamicSharedMemorySize, DSMEM_SZ);

    // Launch order: harness issues 2 launches before ours; ncu (-s 5 -c 1)
    // captures MY index 3 -> the combined QKV GEMM.
    ln_kernel<<<M_, 256>>>(x, ln1w, ln1b, nh);                               // 0
    wconvT3<<<dim3(32, 32, 3), 256>>>(Wq, Wk, Wv, wqkv);                     // 1
    ab_kernel<<<M_, 128>>>(nh, Wb, Wa, al_, be_);                            // 2

    dim3 gqkv(3072/128, M_/128);   // (24, 128)
    tc_gemm<0><<<gqkv, 256, DSMEM_SZ>>>(nh, wqkv, nullptr, nullptr, qkv_, nullptr, M_, 3072, 1024); // 3 <- PROFILED

    act_qkv_kernel<<<M_*H_, 128>>>(qkv_, q_, k_, v_);                        // 4

    recur_kernel<<<B_*H_*4, 128>>>(q_, k_, v_, al_, be_, o_);                // 5

    conv_kernel<<<(M_*1024/4 + 255)/256, 256>>>(o_, oh, M_*1024/4);          // 6
    wconvT<<<dim3(1024/32, 1024/32), 256>>>(Wo, wo, 1024, 1024);             // 7

    dim3 g1(1024/128, M_/128);     // (8, 128)
    tc_gemm<1><<<g1, 256, DSMEM_SZ>>>(oh, wo, nullptr, x, x1_, nullptr, M_, 1024, 1024); // 8

    ln_kernel<<<M_, 256>>>(x1_, ln2w, ln2b, hh);                             // 9

    wconvT<<<dim3(4096/32, 1024/32), 256>>>(W1, w1, 1024, 4096);             // 10
    wconvT<<<dim3(1024/32, 4096/32), 256>>>(W2, w2, 4096, 1024);             // 11

    dim3 g2(4096/128, M_/128);     // (32, 128)
    tc_gemm<2><<<g2, 256, DSMEM_SZ>>>(hh, w1, b1, nullptr, nullptr, fh, M_, 4096, 1024); // 12
    tc_gemm<3><<<g1, 256, DSMEM_SZ>>>(fh, w2, b2, x1_, out, nullptr, M_, 1024, 4096);    // 13
}

// round 12
// speedup vs baseline: 2.0986x; 1.0054x over previous
#include <cuda_runtime.h>
#include <cuda_fp16.h>
#include <math.h>
#include <stdint.h>

#define B_ 4
#define T_ 4096
#define D_ 1024
#define H_ 8
#define K_ 128
#define V_ 128
#define F_ 4096
#define M_ (B_*T_)   // 16384 rows

// ---------------- scratch (device globals) ----------------
__device__ __align__(128) __half g_nh[(size_t)M_*D_];
__device__ __align__(128) float g_qkv[(size_t)M_*3*D_];
__device__ __align__(128) float g_q [(size_t)M_*H_*K_];
__device__ __align__(128) float g_k [(size_t)M_*H_*K_];
__device__ __align__(128) float g_v [(size_t)M_*H_*V_];
__device__ __align__(128) float g_al[(size_t)M_*H_];
__device__ __align__(128) float g_be[(size_t)M_*H_];
__device__ __align__(128) float g_o [(size_t)M_*H_*V_];
__device__ __align__(128) __half g_oh[(size_t)M_*H_*V_];
__device__ __align__(128) float g_x1[(size_t)M_*D_];
__device__ __align__(128) __half g_hh[(size_t)M_*D_];
__device__ __align__(128) __half g_fh[(size_t)M_*F_];
__device__ __align__(128) __half g_wqkv[(size_t)3*1024*1024];
__device__ __align__(128) __half g_wo[1024*1024];
__device__ __align__(128) __half g_w1[(size_t)4096*1024];
__device__ __align__(128) __half g_w2[(size_t)1024*4096];

// ======================== PTX helpers ========================
__device__ __forceinline__ uint32_t smem_u32(const void* p) {
    uint32_t a;
    asm("{ .reg .u64 t; cvta.to.shared.u64 t, %1; cvt.u32.u64 %0, t; }" : "=r"(a) : "l"(p));
    return a;
}
__device__ __forceinline__ void cp16(uint32_t s, const void* g) {
    asm volatile("cp.async.cg.shared.global [%0], [%1], 16;\n" :: "r"(s), "l"(g));
}
__device__ __forceinline__ void cp_commit() { asm volatile("cp.async.commit_group;\n" ::: "memory"); }
template<int N> __device__ __forceinline__ void cp_wait() {
    asm volatile("cp.async.wait_group %0;\n" :: "n"(N) : "memory");
}
__device__ __forceinline__ void ldsm4(uint32_t& r0, uint32_t& r1, uint32_t& r2, uint32_t& r3, uint32_t addr) {
    asm volatile("ldmatrix.sync.aligned.m8n8.x4.shared.b16 {%0,%1,%2,%3}, [%4];"
        : "=r"(r0), "=r"(r1), "=r"(r2), "=r"(r3) : "r"(addr));
}
__device__ __forceinline__ void mma16816(float* d, const uint32_t* a, const uint32_t* b) {
    asm volatile("mma.sync.aligned.m16n8k16.row.col.f32.f16.f16.f32 "
        "{%0,%1,%2,%3},{%4,%5,%6,%7},{%8,%9},{%0,%1,%2,%3};"
        : "+f"(d[0]), "+f"(d[1]), "+f"(d[2]), "+f"(d[3])
        : "r"(a[0]), "r"(a[1]), "r"(a[2]), "r"(a[3]), "r"(b[0]), "r"(b[1]));
}
__device__ __forceinline__ float silu_f(float x) {
    return x / (1.f + __expf(-x));
}

// ======================== HMMA GEMM (unchanged from R9 best) ========================
#define ROWB 80
#define ARR_B (128*ROWB)
#define STG_B (2*ARR_B)
#define NSTAGE 3
#define DSMEM_SZ (NSTAGE*STG_B + 1024)

template<int EPI>
__global__ __launch_bounds__(256, 2) void tc_gemm(
    const __half* __restrict__ A, const __half* __restrict__ Bw,
    const float* __restrict__ bias, const float* __restrict__ resid,
    float* __restrict__ C, __half* __restrict__ Ch,
    int M, int N, int Kd)
{
    extern __shared__ __align__(1024) char dsm_raw[];
    const int tid = threadIdx.x;
    const int wid = tid >> 5, lane = tid & 31;
    const int row0 = blockIdx.y * 128;
    const int col0 = blockIdx.x * 128;
    const int NC = Kd >> 5;

    uint32_t sbase = smem_u32(dsm_raw);
    sbase = (sbase + 1023) & ~1023u;

    const int wm0 = (wid >> 1) * 32;
    const int wn0 = (wid & 1) * 64;

    float acc[2][8][4];
    #pragma unroll
    for (int i = 0; i < 2; i++)
        #pragma unroll
        for (int j = 0; j < 8; j++)
            #pragma unroll
            for (int r = 0; r < 4; r++) acc[i][j][r] = 0.f;

    auto load_chunk = [&](int c) {
        const int kb = c << 5;
        const uint32_t sb = sbase + (c % NSTAGE) * STG_B;
        #pragma unroll
        for (int arr = 0; arr < 2; arr++) {
            const __half* src = (arr == 0) ? A : Bw;
            const int rb = (arr == 0) ? row0 : col0;
            #pragma unroll
            for (int i2 = 0; i2 < 2; i2++) {
                int idx = tid + i2 * 256;
                int row = idx >> 2, seg = idx & 3;
                cp16(sb + arr * ARR_B + row * ROWB + seg * 16,
                     src + (size_t)(rb + row) * Kd + kb + seg * 8);
            }
        }
        cp_commit();
    };

    load_chunk(0);
    load_chunk(1);

    const int sub = lane >> 3, r8 = lane & 7;

    for (int c = 0; c < NC; c++) {
        if (c + 2 < NC) load_chunk(c + 2);
        if (c + 2 < NC) cp_wait<2>();
        else if (c + 1 < NC) cp_wait<1>();
        else cp_wait<0>();
        __syncthreads();

        const uint32_t sb = sbase + (c % NSTAGE) * STG_B;
        #pragma unroll
        for (int kk = 0; kk < 2; kk++) {
            const int kbyte = kk * 32;
            uint32_t af[2][4];
            #pragma unroll
            for (int mi = 0; mi < 2; mi++) {
                int row = wm0 + mi * 16 + (sub & 1) * 8 + r8;
                uint32_t off = row * ROWB + kbyte + (sub >> 1) * 16;
                ldsm4(af[mi][0], af[mi][1], af[mi][2], af[mi][3], sb + off);
            }
            uint32_t bf[8][2];
            #pragma unroll
            for (int nj = 0; nj < 4; nj++) {
                int row = wn0 + nj * 16 + (sub >> 1) * 8 + r8;
                uint32_t off = row * ROWB + kbyte + (sub & 1) * 16;
                ldsm4(bf[nj*2][0], bf[nj*2][1], bf[nj*2+1][0], bf[nj*2+1][1], sb + ARR_B + off);
            }
            #pragma unroll
            for (int mi = 0; mi < 2; mi++)
                #pragma unroll
                for (int ni = 0; ni < 8; ni++)
                    mma16816(acc[mi][ni], af[mi], bf[ni]);
        }
        __syncthreads();
    }

    const int bcol0 = col0 + wn0;
    float2 bv[8];
    if (EPI == 2 || EPI == 3) {
        #pragma unroll
        for (int ni = 0; ni < 8; ni++)
            bv[ni] = *(const float2*)(bias + bcol0 + ni * 8 + (lane & 3) * 2);
    }
    #pragma unroll
    for (int mi = 0; mi < 2; mi++) {
        #pragma unroll
        for (int hf = 0; hf < 2; hf++) {
            const int row = row0 + wm0 + mi * 16 + hf * 8 + (lane >> 2);
            #pragma unroll
            for (int ni = 0; ni < 8; ni++) {
                const int col = bcol0 + ni * 8 + (lane & 3) * 2;
                float y0 = acc[mi][ni][hf*2];
                float y1 = acc[mi][ni][hf*2+1];
                if (EPI == 2 || EPI == 3) { y0 += bv[ni].x; y1 += bv[ni].y; }
                if (EPI == 2) {
                    y0 = 0.5f*y0*(1.f + erff(y0*0.70710678118f));
                    y1 = 0.5f*y1*(1.f + erff(y1*0.70710678118f));
                }
                if (EPI == 1 || EPI == 3) {
                    float2 rv = *(const float2*)(resid + (size_t)row * N + col);
                    y0 += rv.x; y1 += rv.y;
                }
                if (EPI == 2) {
                    __half2 hh(__float2half_rn(y0), __float2half_rn(y1));
                    *(uint32_t*)(Ch + (size_t)row * N + col) = *(uint32_t*)&hh;
                } else {
                    *(float2*)(C + (size_t)row * N + col) = make_float2(y0, y1);
                }
            }
        }
    }
}

// ---------------- LayerNorm -> fp16 ----------------
__global__ __launch_bounds__(256) void ln_kernel(const float* __restrict__ x,
    const float* __restrict__ w, const float* __restrict__ bb,
    __half* __restrict__ oh)
{
    __shared__ float rs[8], rs2[8];
    int row = blockIdx.x, tid = threadIdx.x;
    const float4* xr = (const float4*)(x + (size_t)row * D_);
    float4 v = xr[tid];
    float s  = v.x + v.y + v.z + v.w;
    float s2 = v.x*v.x + v.y*v.y + v.z*v.z + v.w*v.w;
    #pragma unroll
    for (int m = 16; m; m >>= 1) {
        s  += __shfl_xor_sync(~0u, s,  m);
        s2 += __shfl_xor_sync(~0u, s2, m);
    }
    if ((tid & 31) == 0) { rs[tid>>5] = s; rs2[tid>>5] = s2; }
    __syncthreads();
    s = 0.f; s2 = 0.f;
    #pragma unroll
    for (int i = 0; i < 8; i++) { s += rs[i]; s2 += rs2[i]; }
    float mean = s * (1.0f/D_);
    float var  = s2 * (1.0f/D_) - mean*mean;
    float inv  = rsqrtf(var + 1e-5f);
    float4 wv = ((const float4*)w)[tid];
    float4 bv = ((const float4*)bb)[tid];
    float o0 = (v.x-mean)*inv*wv.x + bv.x;
    float o1 = (v.y-mean)*inv*wv.y + bv.y;
    float o2 = (v.z-mean)*inv*wv.z + bv.z;
    float o3 = (v.w-mean)*inv*wv.w + bv.w;
    __half2 h0(__float2half_rn(o0), __float2half_rn(o1));
    __half2 h1(__float2half_rn(o2), __float2half_rn(o3));
    ((uint2*)(oh + (size_t)row * D_))[tid] = make_uint2(*(uint32_t*)&h0, *(uint32_t*)&h1);
}

// ---------------- weight transpose: W[K,N] fp32 -> [N,K] fp16 ----------------
__global__ __launch_bounds__(256) void wconvT(const float* __restrict__ W,
    __half* __restrict__ WT, int Kd, int N)
{
    __shared__ float t[32][33];
    int n0 = blockIdx.x * 32, k0 = blockIdx.y * 32;
    int tx = threadIdx.x & 31, ty = threadIdx.x >> 5;
    #pragma unroll
    for (int i = 0; i < 4; i++)
        t[ty + 8*i][tx] = W[(size_t)(k0 + ty + 8*i) * N + n0 + tx];
    __syncthreads();
    #pragma unroll
    for (int i = 0; i < 4; i++)
        WT[(size_t)(n0 + ty + 8*i) * Kd + k0 + tx] = __float2half_rn(t[tx][ty + 8*i]);
}

// ---------------- combined QKV weight transpose ----------------
__global__ __launch_bounds__(256) void wconvT3(const float* __restrict__ Wq,
    const float* __restrict__ Wk, const float* __restrict__ Wv,
    __half* __restrict__ WT)
{
    __shared__ float t[32][33];
    const float* W = (blockIdx.z == 0) ? Wq : (blockIdx.z == 1) ? Wk : Wv;
    __half* dst = WT + (size_t)blockIdx.z * 1024 * 1024;
    int n0 = blockIdx.x * 32, k0 = blockIdx.y * 32;
    int tx = threadIdx.x & 31, ty = threadIdx.x >> 5;
    #pragma unroll
    for (int i = 0; i < 4; i++)
        t[ty + 8*i][tx] = W[(size_t)(k0 + ty + 8*i) * 1024 + n0 + tx];
    __syncthreads();
    #pragma unroll
    for (int i = 0; i < 4; i++)
        dst[(size_t)(n0 + ty + 8*i) * 1024 + k0 + tx] = __float2half_rn(t[tx][ty + 8*i]);
}

// ---------------- alpha/beta: sigmoid(n @ W{a,b}) ----------------
__global__ __launch_bounds__(128) void ab_kernel(const __half* __restrict__ n,
    const float* __restrict__ Wb, const float* __restrict__ Wa,
    float* __restrict__ al, float* __restrict__ be)
{
    int row = blockIdx.x, tid = threadIdx.x;
    int g = tid >> 3, l = tid & 7;
    const float* W = (g < 8) ? Wb : Wa;
    int c = g & 7;
    const __half* nr = n + (size_t)row * D_;
    float s = 0.f;
    for (int d = l; d < D_; d += 8) s = fmaf(__half2float(nr[d]), W[d*H_ + c], s);
    s += __shfl_xor_sync(~0u, s, 1);
    s += __shfl_xor_sync(~0u, s, 2);
    s += __shfl_xor_sync(~0u, s, 4);
    if (l == 0) {
        float sig = 1.f/(1.f + __expf(-s));
        if (g < 8) be[(size_t)row*H_ + c] = sig;
        else       al[(size_t)row*H_ + c] = sig;
    }
}

// ---------------- silu + l2norm on q,k; silu on v ----------------
__global__ __launch_bounds__(128) void act_qkv_kernel(const float* __restrict__ qkv,
    float* __restrict__ q, float* __restrict__ kk, float* __restrict__ v)
{
    __shared__ float rq[4], rk[4];
    int row = blockIdx.x, tid = threadIdx.x;
    int m = row >> 3, h = row & 7;
    const float* src = qkv + (size_t)m * 3072 + h * 128;
    float xq = src[tid], xk = src[1024 + tid], xv = src[2048 + tid];
    float yq = silu_f(xq);
    float yk = silu_f(xk);
    float sq = yq*yq, sk2 = yk*yk;
    #pragma unroll
    for (int mm = 16; mm; mm >>= 1) {
        sq  += __shfl_xor_sync(~0u, sq,  mm);
        sk2 += __shfl_xor_sync(~0u, sk2, mm);
    }
    if ((tid & 31) == 0) { rq[tid>>5] = sq; rk[tid>>5] = sk2; }
    __syncthreads();
    float nq = rq[0]+rq[1]+rq[2]+rq[3];
    float nk = rk[0]+rk[1]+rk[2]+rk[3];
    size_t idx = (size_t)row*128 + tid;
    q[idx]  = yq * rsqrtf(nq + 1e-6f);
    kk[idx] = yk * rsqrtf(nk + 1e-6f);
    v[idx]  = silu_f(xv);
}

// ---------------- elementwise fp32 -> fp16 ----------------
__global__ __launch_bounds__(256) void conv_kernel(const float* __restrict__ x,
    __half* __restrict__ h, int n4)
{
    int i = blockIdx.x * 256 + threadIdx.x;
    if (i >= n4) return;
    float4 v = ((const float4*)x)[i];
    __half2 h0(__float2half_rn(v.x), __float2half_rn(v.y));
    __half2 h1(__float2half_rn(v.z), __float2half_rn(v.w));
    ((uint2*)h)[i] = make_uint2(*(uint32_t*)&h0, *(uint32_t*)&h1);
}

// ---------------- gated delta-rule recurrence ----------------
// 256 blocks: bh = blk>>3 (32), split = blk&7 (8 x 16 V-cols).
// 128 threads: col = tid>>3 (16 cols), r8 = tid&7 (8 groups x 16 rows).
// ~2 blocks/SM -> 2 warps/SMSP: co-resident block hides the other's stalls.
// Skew 20 floats/group: 8 distinct float4 reads cover all 32 banks once.
// Order per step: kv -> S update -> o -> stage(t+1) -> barrier  (no WAR race:
// all reads of buf complete before the barrier; next iter's writes to buf
// come after it).
__global__ __launch_bounds__(128) void recur_kernel(
    const float* __restrict__ q, const float* __restrict__ k, const float* __restrict__ v,
    const float* __restrict__ al, const float* __restrict__ be, float* __restrict__ o)
{
    __shared__ __align__(16) float sk[2][160];
    __shared__ __align__(16) float sq[2][160];
    __shared__ float sv[2][16];
    __shared__ float sab[2][2];

    int blk = blockIdx.x;
    int bh = blk >> 3, split = blk & 7;
    int b = bh >> 3, h = bh & 7;
    int tid = threadIdx.x;
    int col = tid >> 3, r8 = tid & 7;
    int rbase = r8 * 20;
    int sidx = (tid >> 4) * 20 + (tid & 15);
    size_t base  = ((size_t)b * T_ * H_ + h) * (size_t)K_;
    size_t abase = ((size_t)b * T_) * H_ + h;

    float S[16];
    #pragma unroll
    for (int i = 0; i < 16; i++) S[i] = 0.f;

    sk[0][sidx] = k[base + tid];
    sq[0][sidx] = q[base + tid];
    if (tid < 16) sv[0][tid] = v[base + split*16 + tid];
    if (tid == 0) { sab[0][0] = al[abase]; sab[0][1] = be[abase]; }
    __syncthreads();

    int buf = 0;
    for (int t = 0; t < T_; t++) {
        // issue prefetch t+1 (consumed at staging, end of this iter)
        float pk = 0.f, pq = 0.f, pv = 0.f, pa = 0.f, pb = 0.f;
        if (t + 1 < T_) {
            size_t off = base + (size_t)(t+1) * (H_*K_);
            pk = k[off + tid];
            pq = q[off + tid];
            if (tid < 16) pv = v[off + split*16 + tid];
            if (tid == 0) {
                pa = al[abase + (size_t)(t+1)*H_];
                pb = be[abase + (size_t)(t+1)*H_];
            }
        }
        // kv = k . S over this thread's 16 rows, reduce over 8 r8-groups
        float kreg[16];
        float kv0 = 0.f, kv1 = 0.f, kv2 = 0.f, kv3 = 0.f;
        #pragma unroll
        for (int i4 = 0; i4 < 4; i4++) {
            float4 k4 = *(const float4*)(&sk[buf][rbase + i4*4]);
            kreg[i4*4+0] = k4.x; kreg[i4*4+1] = k4.y;
            kreg[i4*4+2] = k4.z; kreg[i4*4+3] = k4.w;
            kv0 = fmaf(k4.x, S[i4*4+0], kv0);
            kv1 = fmaf(k4.y, S[i4*4+1], kv1);
            kv2 = fmaf(k4.z, S[i4*4+2], kv2);
            kv3 = fmaf(k4.w, S[i4*4+3], kv3);
        }
        float kv = (kv0+kv1)+(kv2+kv3);
        kv += __shfl_xor_sync(~0u, kv, 1);
        kv += __shfl_xor_sync(~0u, kv, 2);
        kv += __shfl_xor_sync(~0u, kv, 4);
        float a  = sab[buf][0], bt = sab[buf][1];
        float w  = bt * (sv[buf][col] - a * kv);
        #pragma unroll
        for (int i = 0; i < 16; i++) S[i] = fmaf(a, S[i], kreg[i]*w);
        // o = q . S (post-update)
        float o0 = 0.f, o1 = 0.f, o2 = 0.f, o3 = 0.f;
        #pragma unroll
        for (int i4 = 0; i4 < 4; i4++) {
            float4 q4 = *(const float4*)(&sq[buf][rbase + i4*4]);
            o0 = fmaf(q4.x, S[i4*4+0], o0);
            o1 = fmaf(q4.y, S[i4*4+1], o1);
            o2 = fmaf(q4.z, S[i4*4+2], o2);
            o3 = fmaf(q4.w, S[i4*4+3], o3);
        }
        float oa = (o0+o1)+(o2+o3);
        oa += __shfl_xor_sync(~0u, oa, 1);
        oa += __shfl_xor_sync(~0u, oa, 2);
        oa += __shfl_xor_sync(~0u, oa, 4);
        if (r8 == 0) o[base + (size_t)t*(H_*K_) + split*16 + col] = oa;
        // stage t+1 into the other buffer, then one barrier
        int nb = buf ^ 1;
        if (t + 1 < T_) {
            sk[nb][sidx] = pk;
            sq[nb][sidx] = pq;
            if (tid < 16) sv[nb][tid] = pv;
            if (tid == 0) { sab[nb][0] = pa; sab[nb][1] = pb; }
        }
        __syncthreads();
        buf = nb;
    }
}

// ---------------- launch ----------------
extern "C" void kernel_launch(void* const* d_in, const int* in_sizes, int n_in,
                              void* d_out, int out_size)
{
    const float* x    = (const float*)d_in[0];
    const float* Wq   = (const float*)d_in[1];
    const float* Wk   = (const float*)d_in[2];
    const float* Wv   = (const float*)d_in[3];
    const float* Wb   = (const float*)d_in[4];
    const float* Wa   = (const float*)d_in[5];
    const float* Wo   = (const float*)d_in[6];
    const float* ln1w = (const float*)d_in[7];
    const float* ln1b = (const float*)d_in[8];
    const float* ln2w = (const float*)d_in[9];
    const float* ln2b = (const float*)d_in[10];
    const float* W1   = (const float*)d_in[11];
    const float* b1   = (const float*)d_in[12];
    const float* W2   = (const float*)d_in[13];
    const float* b2   = (const float*)d_in[14];
    float* out = (float*)d_out;

    float *qkv_, *q_, *k_, *v_, *al_, *be_, *o_, *x1_;
    __half *nh, *oh, *hh, *fh, *wqkv, *wo, *w1, *w2;
    cudaGetSymbolAddress((void**)&nh,   g_nh);
    cudaGetSymbolAddress((void**)&qkv_, g_qkv);
    cudaGetSymbolAddress((void**)&q_,   g_q);
    cudaGetSymbolAddress((void**)&k_,   g_k);
    cudaGetSymbolAddress((void**)&v_,   g_v);
    cudaGetSymbolAddress((void**)&al_,  g_al);
    cudaGetSymbolAddress((void**)&be_,  g_be);
    cudaGetSymbolAddress((void**)&o_,   g_o);
    cudaGetSymbolAddress((void**)&oh,   g_oh);
    cudaGetSymbolAddress((void**)&x1_,  g_x1);
    cudaGetSymbolAddress((void**)&hh,   g_hh);
    cudaGetSymbolAddress((void**)&fh,   g_fh);
    cudaGetSymbolAddress((void**)&wqkv, g_wqkv);
    cudaGetSymbolAddress((void**)&wo,   g_wo);
    cudaGetSymbolAddress((void**)&w1,   g_w1);
    cudaGetSymbolAddress((void**)&w2,   g_w2);

    cudaFuncSetAttribute(tc_gemm<0>, cudaFuncAttributeMaxDynamicSharedMemorySize, DSMEM_SZ);
    cudaFuncSetAttribute(tc_gemm<1>, cudaFuncAttributeMaxDynamicSharedMemorySize, DSMEM_SZ);
    cudaFuncSetAttribute(tc_gemm<2>, cudaFuncAttributeMaxDynamicSharedMemorySize, DSMEM_SZ);
    cudaFuncSetAttribute(tc_gemm<3>, cudaFuncAttributeMaxDynamicSharedMemorySize, DSMEM_SZ);

    ln_kernel<<<M_, 256>>>(x, ln1w, ln1b, nh);                               // 0
    wconvT3<<<dim3(32, 32, 3), 256>>>(Wq, Wk, Wv, wqkv);                     // 1
    ab_kernel<<<M_, 128>>>(nh, Wb, Wa, al_, be_);                            // 2

    dim3 gqkv(3072/128, M_/128);
    tc_gemm<0><<<gqkv, 256, DSMEM_SZ>>>(nh, wqkv, nullptr, nullptr, qkv_, nullptr, M_, 3072, 1024); // 3 <- PROFILED

    act_qkv_kernel<<<M_*H_, 128>>>(qkv_, q_, k_, v_);                        // 4

    recur_kernel<<<B_*H_*8, 128>>>(q_, k_, v_, al_, be_, o_);                // 5

    conv_kernel<<<(M_*1024/4 + 255)/256, 256>>>(o_, oh, M_*1024/4);          // 6
    wconvT<<<dim3(1024/32, 1024/32), 256>>>(Wo, wo, 1024, 1024);             // 7

    dim3 g1(1024/128, M_/128);
    tc_gemm<1><<<g1, 256, DSMEM_SZ>>>(oh, wo, nullptr, x, x1_, nullptr, M_, 1024, 1024); // 8

    ln_kernel<<<M_, 256>>>(x1_, ln2w, ln2b, hh);                             // 9

    wconvT<<<dim3(4096/32, 1024/32), 256>>>(W1, w1, 1024, 4096);             // 10
    wconvT<<<dim3(1024/32, 4096/32), 256>>>(W2, w2, 4096, 1024);             // 11

    dim3 g2(4096/128, M_/128);
    tc_gemm<2><<<g2, 256, DSMEM_SZ>>>(hh, w1, b1, nullptr, nullptr, fh, M_, 4096, 1024); // 12
    tc_gemm<3><<<g1, 256, DSMEM_SZ>>>(fh, w2, b2, x1_, out, nullptr, M_, 1024, 4096);    // 13
}

// round 13
// speedup vs baseline: 3.2300x; 1.5392x over previous
#include <cuda_runtime.h>
#include <cuda_fp16.h>
#include <math.h>
#include <stdint.h>

#define B_ 4
#define T_ 4096
#define D_ 1024
#define H_ 8
#define K_ 128
#define V_ 128
#define F_ 4096
#define M_ (B_*T_)   // 16384 rows
#define NTC 32       // recurrence timesteps per smem chunk

// ---------------- scratch (device globals) ----------------
__device__ __align__(128) __half g_nh[(size_t)M_*D_];
__device__ __align__(128) float g_qkv[(size_t)M_*3*D_];
__device__ __align__(128) __half g_qh[(size_t)M_*H_*K_];
__device__ __align__(128) __half g_kh[(size_t)M_*H_*K_];
__device__ __align__(128) __half g_vh[(size_t)M_*H_*V_];
__device__ __align__(128) float g_al[(size_t)B_*H_*T_];   // transposed [B*H, T]
__device__ __align__(128) float g_be[(size_t)B_*H_*T_];
__device__ __align__(128) __half g_oh[(size_t)M_*H_*V_];
__device__ __align__(128) float g_x1[(size_t)M_*D_];
__device__ __align__(128) __half g_hh[(size_t)M_*D_];
__device__ __align__(128) __half g_fh[(size_t)M_*F_];
__device__ __align__(128) __half g_wqkv[(size_t)3*1024*1024];
__device__ __align__(128) __half g_wo[1024*1024];
__device__ __align__(128) __half g_w1[(size_t)4096*1024];
__device__ __align__(128) __half g_w2[(size_t)1024*4096];

// ======================== PTX helpers ========================
__device__ __forceinline__ uint32_t smem_u32(const void* p) {
    uint32_t a;
    asm("{ .reg .u64 t; cvta.to.shared.u64 t, %1; cvt.u32.u64 %0, t; }" : "=r"(a) : "l"(p));
    return a;
}
__device__ __forceinline__ void cp16(uint32_t s, const void* g) {
    asm volatile("cp.async.cg.shared.global [%0], [%1], 16;\n" :: "r"(s), "l"(g));
}
__device__ __forceinline__ void cp_commit() { asm volatile("cp.async.commit_group;\n" ::: "memory"); }
template<int N> __device__ __forceinline__ void cp_wait() {
    asm volatile("cp.async.wait_group %0;\n" :: "n"(N) : "memory");
}
__device__ __forceinline__ void ldsm4(uint32_t& r0, uint32_t& r1, uint32_t& r2, uint32_t& r3, uint32_t addr) {
    asm volatile("ldmatrix.sync.aligned.m8n8.x4.shared.b16 {%0,%1,%2,%3}, [%4];"
        : "=r"(r0), "=r"(r1), "=r"(r2), "=r"(r3) : "r"(addr));
}
__device__ __forceinline__ void mma16816(float* d, const uint32_t* a, const uint32_t* b) {
    asm volatile("mma.sync.aligned.m16n8k16.row.col.f32.f16.f16.f32 "
        "{%0,%1,%2,%3},{%4,%5,%6,%7},{%8,%9},{%0,%1,%2,%3};"
        : "+f"(d[0]), "+f"(d[1]), "+f"(d[2]), "+f"(d[3])
        : "r"(a[0]), "r"(a[1]), "r"(a[2]), "r"(a[3]), "r"(b[0]), "r"(b[1]));
}
__device__ __forceinline__ float silu_f(float x) {
    return x / (1.f + __expf(-x));
}

// ======================== HMMA GEMM (unchanged, R9-best) ========================
#define ROWB 80
#define ARR_B (128*ROWB)
#define STG_B (2*ARR_B)
#define NSTAGE 3
#define DSMEM_SZ (NSTAGE*STG_B + 1024)

template<int EPI>
__global__ __launch_bounds__(256, 2) void tc_gemm(
    const __half* __restrict__ A, const __half* __restrict__ Bw,
    const float* __restrict__ bias, const float* __restrict__ resid,
    float* __restrict__ C, __half* __restrict__ Ch,
    int M, int N, int Kd)
{
    extern __shared__ __align__(1024) char dsm_raw[];
    const int tid = threadIdx.x;
    const int wid = tid >> 5, lane = tid & 31;
    const int row0 = blockIdx.y * 128;
    const int col0 = blockIdx.x * 128;
    const int NC = Kd >> 5;

    uint32_t sbase = smem_u32(dsm_raw);
    sbase = (sbase + 1023) & ~1023u;

    const int wm0 = (wid >> 1) * 32;
    const int wn0 = (wid & 1) * 64;

    float acc[2][8][4];
    #pragma unroll
    for (int i = 0; i < 2; i++)
        #pragma unroll
        for (int j = 0; j < 8; j++)
            #pragma unroll
            for (int r = 0; r < 4; r++) acc[i][j][r] = 0.f;

    auto load_chunk = [&](int c) {
        const int kb = c << 5;
        const uint32_t sb = sbase + (c % NSTAGE) * STG_B;
        #pragma unroll
        for (int arr = 0; arr < 2; arr++) {
            const __half* src = (arr == 0) ? A : Bw;
            const int rb = (arr == 0) ? row0 : col0;
            #pragma unroll
            for (int i2 = 0; i2 < 2; i2++) {
                int idx = tid + i2 * 256;
                int row = idx >> 2, seg = idx & 3;
                cp16(sb + arr * ARR_B + row * ROWB + seg * 16,
                     src + (size_t)(rb + row) * Kd + kb + seg * 8);
            }
        }
        cp_commit();
    };

    load_chunk(0);
    load_chunk(1);

    const int sub = lane >> 3, r8 = lane & 7;

    for (int c = 0; c < NC; c++) {
        if (c + 2 < NC) load_chunk(c + 2);
        if (c + 2 < NC) cp_wait<2>();
        else if (c + 1 < NC) cp_wait<1>();
        else cp_wait<0>();
        __syncthreads();

        const uint32_t sb = sbase + (c % NSTAGE) * STG_B;
        #pragma unroll
        for (int kk = 0; kk < 2; kk++) {
            const int kbyte = kk * 32;
            uint32_t af[2][4];
            #pragma unroll
            for (int mi = 0; mi < 2; mi++) {
                int row = wm0 + mi * 16 + (sub & 1) * 8 + r8;
                uint32_t off = row * ROWB + kbyte + (sub >> 1) * 16;
                ldsm4(af[mi][0], af[mi][1], af[mi][2], af[mi][3], sb + off);
            }
            uint32_t bf[8][2];
            #pragma unroll
            for (int nj = 0; nj < 4; nj++) {
                int row = wn0 + nj * 16 + (sub >> 1) * 8 + r8;
                uint32_t off = row * ROWB + kbyte + (sub & 1) * 16;
                ldsm4(bf[nj*2][0], bf[nj*2][1], bf[nj*2+1][0], bf[nj*2+1][1], sb + ARR_B + off);
            }
            #pragma unroll
            for (int mi = 0; mi < 2; mi++)
                #pragma unroll
                for (int ni = 0; ni < 8; ni++)
                    mma16816(acc[mi][ni], af[mi], bf[ni]);
        }
        __syncthreads();
    }

    const int bcol0 = col0 + wn0;
    float2 bv[8];
    if (EPI == 2 || EPI == 3) {
        #pragma unroll
        for (int ni = 0; ni < 8; ni++)
            bv[ni] = *(const float2*)(bias + bcol0 + ni * 8 + (lane & 3) * 2);
    }
    #pragma unroll
    for (int mi = 0; mi < 2; mi++) {
        #pragma unroll
        for (int hf = 0; hf < 2; hf++) {
            const int row = row0 + wm0 + mi * 16 + hf * 8 + (lane >> 2);
            #pragma unroll
            for (int ni = 0; ni < 8; ni++) {
                const int col = bcol0 + ni * 8 + (lane & 3) * 2;
                float y0 = acc[mi][ni][hf*2];
                float y1 = acc[mi][ni][hf*2+1];
                if (EPI == 2 || EPI == 3) { y0 += bv[ni].x; y1 += bv[ni].y; }
                if (EPI == 2) {
                    y0 = 0.5f*y0*(1.f + erff(y0*0.70710678118f));
                    y1 = 0.5f*y1*(1.f + erff(y1*0.70710678118f));
                }
                if (EPI == 1 || EPI == 3) {
                    float2 rv = *(const float2*)(resid + (size_t)row * N + col);
                    y0 += rv.x; y1 += rv.y;
                }
                if (EPI == 2) {
                    __half2 hh(__float2half_rn(y0), __float2half_rn(y1));
                    *(uint32_t*)(Ch + (size_t)row * N + col) = *(uint32_t*)&hh;
                } else {
                    *(float2*)(C + (size_t)row * N + col) = make_float2(y0, y1);
                }
            }
        }
    }
}

// ---------------- LayerNorm -> fp16 ----------------
__global__ __launch_bounds__(256) void ln_kernel(const float* __restrict__ x,
    const float* __restrict__ w, const float* __restrict__ bb,
    __half* __restrict__ oh)
{
    __shared__ float rs[8], rs2[8];
    int row = blockIdx.x, tid = threadIdx.x;
    const float4* xr = (const float4*)(x + (size_t)row * D_);
    float4 v = xr[tid];
    float s  = v.x + v.y + v.z + v.w;
    float s2 = v.x*v.x + v.y*v.y + v.z*v.z + v.w*v.w;
    #pragma unroll
    for (int m = 16; m; m >>= 1) {
        s  += __shfl_xor_sync(~0u, s,  m);
        s2 += __shfl_xor_sync(~0u, s2, m);
    }
    if ((tid & 31) == 0) { rs[tid>>5] = s; rs2[tid>>5] = s2; }
    __syncthreads();
    s = 0.f; s2 = 0.f;
    #pragma unroll
    for (int i = 0; i < 8; i++) { s += rs[i]; s2 += rs2[i]; }
    float mean = s * (1.0f/D_);
    float var  = s2 * (1.0f/D_) - mean*mean;
    float inv  = rsqrtf(var + 1e-5f);
    float4 wv = ((const float4*)w)[tid];
    float4 bv = ((const float4*)bb)[tid];
    float o0 = (v.x-mean)*inv*wv.x + bv.x;
    float o1 = (v.y-mean)*inv*wv.y + bv.y;
    float o2 = (v.z-mean)*inv*wv.z + bv.z;
    float o3 = (v.w-mean)*inv*wv.w + bv.w;
    __half2 h0(__float2half_rn(o0), __float2half_rn(o1));
    __half2 h1(__float2half_rn(o2), __float2half_rn(o3));
    ((uint2*)(oh + (size_t)row * D_))[tid] = make_uint2(*(uint32_t*)&h0, *(uint32_t*)&h1);
}

// ---------------- weight transpose ----------------
__global__ __launch_bounds__(256) void wconvT(const float* __restrict__ W,
    __half* __restrict__ WT, int Kd, int N)
{
    __shared__ float t[32][33];
    int n0 = blockIdx.x * 32, k0 = blockIdx.y * 32;
    int tx = threadIdx.x & 31, ty = threadIdx.x >> 5;
    #pragma unroll
    for (int i = 0; i < 4; i++)
        t[ty + 8*i][tx] = W[(size_t)(k0 + ty + 8*i) * N + n0 + tx];
    __syncthreads();
    #pragma unroll
    for (int i = 0; i < 4; i++)
        WT[(size_t)(n0 + ty + 8*i) * Kd + k0 + tx] = __float2half_rn(t[tx][ty + 8*i]);
}

__global__ __launch_bounds__(256) void wconvT3(const float* __restrict__ Wq,
    const float* __restrict__ Wk, const float* __restrict__ Wv,
    __half* __restrict__ WT)
{
    __shared__ float t[32][33];
    const float* W = (blockIdx.z == 0) ? Wq : (blockIdx.z == 1) ? Wk : Wv;
    __half* dst = WT + (size_t)blockIdx.z * 1024 * 1024;
    int n0 = blockIdx.x * 32, k0 = blockIdx.y * 32;
    int tx = threadIdx.x & 31, ty = threadIdx.x >> 5;
    #pragma unroll
    for (int i = 0; i < 4; i++)
        t[ty + 8*i][tx] = W[(size_t)(k0 + ty + 8*i) * 1024 + n0 + tx];
    __syncthreads();
    #pragma unroll
    for (int i = 0; i < 4; i++)
        dst[(size_t)(n0 + ty + 8*i) * 1024 + k0 + tx] = __float2half_rn(t[tx][ty + 8*i]);
}

// ---------------- alpha/beta: sigmoid(n @ W{a,b}) -> transposed [B*H, T] --------
__global__ __launch_bounds__(128) void ab_kernel(const __half* __restrict__ n,
    const float* __restrict__ Wb, const float* __restrict__ Wa,
    float* __restrict__ alT, float* __restrict__ beT)
{
    int row = blockIdx.x, tid = threadIdx.x;     // row = b*T + t
    int g = tid >> 3, l = tid & 7;
    const float* W = (g < 8) ? Wb : Wa;
    int c = g & 7;
    const __half* nr = n + (size_t)row * D_;
    float s = 0.f;
    for (int d = l; d < D_; d += 8) s = fmaf(__half2float(nr[d]), W[d*H_ + c], s);
    s += __shfl_xor_sync(~0u, s, 1);
    s += __shfl_xor_sync(~0u, s, 2);
    s += __shfl_xor_sync(~0u, s, 4);
    if (l == 0) {
        float sig = 1.f/(1.f + __expf(-s));
        int b = row >> 12, t = row & (T_ - 1);
        size_t oidx = ((size_t)(b * H_ + c)) * T_ + t;
        if (g < 8) beT[oidx] = sig;
        else       alT[oidx] = sig;
    }
}

// ---------------- silu + l2norm on q,k; silu on v -> fp16 ----------------
__global__ __launch_bounds__(128) void act_qkv_kernel(const float* __restrict__ qkv,
    __half* __restrict__ q, __half* __restrict__ kk, __half* __restrict__ v)
{
    __shared__ float rq[4], rk[4];
    int row = blockIdx.x, tid = threadIdx.x;
    int m = row >> 3, h = row & 7;
    const float* src = qkv + (size_t)m * 3072 + h * 128;
    float xq = src[tid], xk = src[1024 + tid], xv = src[2048 + tid];
    float yq = silu_f(xq);
    float yk = silu_f(xk);
    float sq = yq*yq, sk2 = yk*yk;
    #pragma unroll
    for (int mm = 16; mm; mm >>= 1) {
        sq  += __shfl_xor_sync(~0u, sq,  mm);
        sk2 += __shfl_xor_sync(~0u, sk2, mm);
    }
    if ((tid & 31) == 0) { rq[tid>>5] = sq; rk[tid>>5] = sk2; }
    __syncthreads();
    float nq = rq[0]+rq[1]+rq[2]+rq[3];
    float nk = rk[0]+rk[1]+rk[2]+rk[3];
    size_t idx = (size_t)row*128 + tid;
    q[idx]  = __float2half(yq * rsqrtf(nq + 1e-6f));
    kk[idx] = __float2half(yk * rsqrtf(nk + 1e-6f));
    v[idx]  = __float2half(silu_f(xv));
}

// ---------------- gated delta-rule recurrence (chunked smem staging) ----------
// 256 blocks: bh = blk>>3, split = blk&7 (16 V-cols each). 128 threads:
// col = tid>>3 (16 cols), r8 = tid&7 (16 state rows each).
// Chunks of NTC=32 steps staged in smem (fp16) via cp.async, double-buffered.
// No per-step barrier: smem read-only within a chunk, reductions shfl-local.
__global__ __launch_bounds__(128) void recur_kernel(
    const __half* __restrict__ q, const __half* __restrict__ k, const __half* __restrict__ v,
    const float* __restrict__ alT, const float* __restrict__ beT, __half* __restrict__ o)
{
    __shared__ __align__(16) __half sk[2][NTC*128];
    __shared__ __align__(16) __half sq[2][NTC*128];
    __shared__ __align__(16) __half sv[2][NTC*16];
    __shared__ __align__(16) float sa[2][NTC];
    __shared__ __align__(16) float sb_[2][NTC];

    const int blk = blockIdx.x;
    const int bh = blk >> 3, split = blk & 7;
    const int b = bh >> 3, h = bh & 7;
    const int tid = threadIdx.x;
    const int col = tid >> 3, r8 = tid & 7;
    const size_t base = ((size_t)b * T_ * H_ + h) * (size_t)K_;   // halves
    const size_t abbase = (size_t)bh * T_;

    auto load_chunk = [&](int c, int d) {
        const char* kc = (const char*)(k + base + (size_t)c * NTC * (H_*K_));
        const char* qc = (const char*)(q + base + (size_t)c * NTC * (H_*K_));
        const char* vc = (const char*)(v + base + (size_t)c * NTC * (H_*K_) + split*16);
        uint32_t skb = smem_u32(&sk[d][0]);
        uint32_t sqb = smem_u32(&sq[d][0]);
        #pragma unroll
        for (int i = 0; i < 4; i++) {
            int idx = tid + i * 128;         // 0..511
            int row = idx >> 4, seg = idx & 15;
            cp16(skb + row*256 + seg*16, kc + (size_t)row*2048 + seg*16);
            cp16(sqb + row*256 + seg*16, qc + (size_t)row*2048 + seg*16);
        }
        if (tid < 64) {
            int row = tid >> 1, seg = tid & 1;
            cp16(smem_u32(&sv[d][0]) + row*32 + seg*16, vc + (size_t)row*2048 + seg*16);
        } else if (tid < 72) {
            int s = tid - 64;
            cp16(smem_u32(&sa[d][0]) + s*16, (const char*)(alT + abbase + c*NTC) + s*16);
        } else if (tid < 80) {
            int s = tid - 72;
            cp16(smem_u32(&sb_[d][0]) + s*16, (const char*)(beT + abbase + c*NTC) + s*16);
        }
        cp_commit();
    };

    float S[16];
    #pragma unroll
    for (int i = 0; i < 16; i++) S[i] = 0.f;

    const int NCH = T_ / NTC;   // 128
    load_chunk(0, 0);

    for (int c = 0; c < NCH; c++) {
        const int d = c & 1;
        if (c + 1 < NCH) { load_chunk(c + 1, d ^ 1); cp_wait<1>(); }
        else cp_wait<0>();
        __syncthreads();

        const char* skd = (const char*)&sk[d][0] + r8 * 32;
        const char* sqd = (const char*)&sq[d][0] + r8 * 32;

        #pragma unroll 2
        for (int tt = 0; tt < NTC; tt++) {
            // --- k row -> fp32 regs + kv partial dot ---
            uint4 k0 = *(const uint4*)(skd + tt*256);
            uint4 k1 = *(const uint4*)(skd + tt*256 + 16);
            float kreg[16];
            {
                const __half2* hp0 = (const __half2*)&k0;
                const __half2* hp1 = (const __half2*)&k1;
                #pragma unroll
                for (int j = 0; j < 4; j++) {
                    float2 f0 = __half22float2(hp0[j]);
                    float2 f1 = __half22float2(hp1[j]);
                    kreg[2*j]   = f0.x; kreg[2*j+1]   = f0.y;
                    kreg[8+2*j] = f1.x; kreg[8+2*j+1] = f1.y;
                }
            }
            float kv0 = 0.f, kv1 = 0.f, kv2 = 0.f, kv3 = 0.f;
            #pragma unroll
            for (int i = 0; i < 4; i++) {
                kv0 = fmaf(kreg[4*i+0], S[4*i+0], kv0);
                kv1 = fmaf(kreg[4*i+1], S[4*i+1], kv1);
                kv2 = fmaf(kreg[4*i+2], S[4*i+2], kv2);
                kv3 = fmaf(kreg[4*i+3], S[4*i+3], kv3);
            }
            float kv = (kv0+kv1)+(kv2+kv3);
            kv += __shfl_xor_sync(~0u, kv, 1);
            kv += __shfl_xor_sync(~0u, kv, 2);
            kv += __shfl_xor_sync(~0u, kv, 4);

            float a  = sa[d][tt], bt = sb_[d][tt];
            float vv = __half2float(sv[d][tt*16 + col]);
            float w  = bt * (vv - a * kv);
            #pragma unroll
            for (int i = 0; i < 16; i++) S[i] = fmaf(a, S[i], kreg[i]*w);

            // --- o = q . S ---
            uint4 q0 = *(const uint4*)(sqd + tt*256);
            uint4 q1 = *(const uint4*)(sqd + tt*256 + 16);
            float o0 = 0.f, o1 = 0.f, o2 = 0.f, o3 = 0.f;
            {
                const __half2* hp0 = (const __half2*)&q0;
                const __half2* hp1 = (const __half2*)&q1;
                #pragma unroll
                for (int j = 0; j < 4; j++) {
                    float2 f0 = __half22float2(hp0[j]);
                    float2 f1 = __half22float2(hp1[j]);
                    o0 = fmaf(f0.x, S[2*j],     o0);
                    o1 = fmaf(f0.y, S[2*j+1],   o1);
                    o2 = fmaf(f1.x, S[8+2*j],   o2);
                    o3 = fmaf(f1.y, S[8+2*j+1], o3);
                }
            }
            float oa = (o0+o1)+(o2+o3);
            oa += __shfl_xor_sync(~0u, oa, 1);
            oa += __shfl_xor_sync(~0u, oa, 2);
            oa += __shfl_xor_sync(~0u, oa, 4);
            if (r8 == 0)
                o[base + (size_t)(c*NTC + tt)*(H_*K_) + split*16 + col] = __float2half(oa);
        }
        __syncthreads();   // all reads of buf d done before next iter overwrites it
    }
}

// ---------------- launch ----------------
extern "C" void kernel_launch(void* const* d_in, const int* in_sizes, int n_in,
                              void* d_out, int out_size)
{
    const float* x    = (const float*)d_in[0];
    const float* Wq   = (const float*)d_in[1];
    const float* Wk   = (const float*)d_in[2];
    const float* Wv   = (const float*)d_in[3];
    const float* Wb   = (const float*)d_in[4];
    const float* Wa   = (const float*)d_in[5];
    const float* Wo   = (const float*)d_in[6];
    const float* ln1w = (const float*)d_in[7];
    const float* ln1b = (const float*)d_in[8];
    const float* ln2w = (const float*)d_in[9];
    const float* ln2b = (const float*)d_in[10];
    const float* W1   = (const float*)d_in[11];
    const float* b1   = (const float*)d_in[12];
    const float* W2   = (const float*)d_in[13];
    const float* b2   = (const float*)d_in[14];
    float* out = (float*)d_out;

    float *qkv_, *al_, *be_, *x1_;
    __half *nh, *qh, *kh, *vh, *oh, *hh, *fh, *wqkv, *wo, *w1, *w2;
    cudaGetSymbolAddress((void**)&nh,   g_nh);
    cudaGetSymbolAddress((void**)&qkv_, g_qkv);
    cudaGetSymbolAddress((void**)&qh,   g_qh);
    cudaGetSymbolAddress((void**)&kh,   g_kh);
    cudaGetSymbolAddress((void**)&vh,   g_vh);
    cudaGetSymbolAddress((void**)&al_,  g_al);
    cudaGetSymbolAddress((void**)&be_,  g_be);
    cudaGetSymbolAddress((void**)&oh,   g_oh);
    cudaGetSymbolAddress((void**)&x1_,  g_x1);
    cudaGetSymbolAddress((void**)&hh,   g_hh);
    cudaGetSymbolAddress((void**)&fh,   g_fh);
    cudaGetSymbolAddress((void**)&wqkv, g_wqkv);
    cudaGetSymbolAddress((void**)&wo,   g_wo);
    cudaGetSymbolAddress((void**)&w1,   g_w1);
    cudaGetSymbolAddress((void**)&w2,   g_w2);

    cudaFuncSetAttribute(tc_gemm<0>, cudaFuncAttributeMaxDynamicSharedMemorySize, DSMEM_SZ);
    cudaFuncSetAttribute(tc_gemm<1>, cudaFuncAttributeMaxDynamicSharedMemorySize, DSMEM_SZ);
    cudaFuncSetAttribute(tc_gemm<2>, cudaFuncAttributeMaxDynamicSharedMemorySize, DSMEM_SZ);
    cudaFuncSetAttribute(tc_gemm<3>, cudaFuncAttributeMaxDynamicSharedMemorySize, DSMEM_SZ);

    ln_kernel<<<M_, 256>>>(x, ln1w, ln1b, nh);                               // 0
    wconvT3<<<dim3(32, 32, 3), 256>>>(Wq, Wk, Wv, wqkv);                     // 1
    ab_kernel<<<M_, 128>>>(nh, Wb, Wa, al_, be_);                            // 2

    dim3 gqkv(3072/128, M_/128);
    tc_gemm<0><<<gqkv, 256, DSMEM_SZ>>>(nh, wqkv, nullptr, nullptr, qkv_, nullptr, M_, 3072, 1024); // 3 <- PROFILED

    act_qkv_kernel<<<M_*H_, 128>>>(qkv_, qh, kh, vh);                        // 4

    recur_kernel<<<B_*H_*8, 128>>>(qh, kh, vh, al_, be_, oh);                // 5

    wconvT<<<dim3(1024/32, 1024/32), 256>>>(Wo, wo, 1024, 1024);             // 6

    dim3 g1(1024/128, M_/128);
    tc_gemm<1><<<g1, 256, DSMEM_SZ>>>(oh, wo, nullptr, x, x1_, nullptr, M_, 1024, 1024); // 7

    ln_kernel<<<M_, 256>>>(x1_, ln2w, ln2b, hh);                             // 8

    wconvT<<<dim3(4096/32, 1024/32), 256>>>(W1, w1, 1024, 4096);             // 9
    wconvT<<<dim3(1024/32, 4096/32), 256>>>(W2, w2, 4096, 1024);             // 10

    dim3 g2(4096/128, M_/128);
    tc_gemm<2><<<g2, 256, DSMEM_SZ>>>(hh, w1, b1, nullptr, nullptr, fh, M_, 4096, 1024); // 11
    tc_gemm<3><<<g1, 256, DSMEM_SZ>>>(fh, w2, b2, x1_, out, nullptr, M_, 1024, 4096);    // 12
}

// round 14
// speedup vs baseline: 3.4803x; 1.0775x over previous
#include <cuda_runtime.h>
#include <cuda_fp16.h>
#include <math.h>
#include <stdint.h>

#define B_ 4
#define T_ 4096
#define D_ 1024
#define H_ 8
#define K_ 128
#define V_ 128
#define F_ 4096
#define M_ (B_*T_)   // 16384 rows
#define NTC 32       // recurrence timesteps per smem chunk

// ---------------- scratch (device globals) ----------------
__device__ __align__(128) __half g_nh[(size_t)M_*D_];
__device__ __align__(128) float g_qkv[(size_t)M_*3*D_];
__device__ __align__(128) __half g_qh[(size_t)M_*H_*K_];
__device__ __align__(128) __half g_kh[(size_t)M_*H_*K_];
__device__ __align__(128) __half g_vh[(size_t)M_*H_*V_];
__device__ __align__(128) float g_al[(size_t)B_*H_*T_];   // transposed [B*H, T]
__device__ __align__(128) float g_be[(size_t)B_*H_*T_];
__device__ __align__(128) __half g_oh[(size_t)M_*H_*V_];
__device__ __align__(128) float g_x1[(size_t)M_*D_];
__device__ __align__(128) __half g_hh[(size_t)M_*D_];
__device__ __align__(128) __half g_fh[(size_t)M_*F_];
__device__ __align__(128) __half g_wqkv[(size_t)3*1024*1024];
__device__ __align__(128) __half g_wo[1024*1024];
__device__ __align__(128) __half g_w1[(size_t)4096*1024];
__device__ __align__(128) __half g_w2[(size_t)1024*4096];

// ======================== PTX helpers ========================
__device__ __forceinline__ uint32_t smem_u32(const void* p) {
    uint32_t a;
    asm("{ .reg .u64 t; cvta.to.shared.u64 t, %1; cvt.u32.u64 %0, t; }" : "=r"(a) : "l"(p));
    return a;
}
__device__ __forceinline__ void cp16(uint32_t s, const void* g) {
    asm volatile("cp.async.cg.shared.global [%0], [%1], 16;\n" :: "r"(s), "l"(g));
}
__device__ __forceinline__ void cp_commit() { asm volatile("cp.async.commit_group;\n" ::: "memory"); }
template<int N> __device__ __forceinline__ void cp_wait() {
    asm volatile("cp.async.wait_group %0;\n" :: "n"(N) : "memory");
}
__device__ __forceinline__ void ldsm4(uint32_t& r0, uint32_t& r1, uint32_t& r2, uint32_t& r3, uint32_t addr) {
    asm volatile("ldmatrix.sync.aligned.m8n8.x4.shared.b16 {%0,%1,%2,%3}, [%4];"
        : "=r"(r0), "=r"(r1), "=r"(r2), "=r"(r3) : "r"(addr));
}
__device__ __forceinline__ void mma16816(float* d, const uint32_t* a, const uint32_t* b) {
    asm volatile("mma.sync.aligned.m16n8k16.row.col.f32.f16.f16.f32 "
        "{%0,%1,%2,%3},{%4,%5,%6,%7},{%8,%9},{%0,%1,%2,%3};"
        : "+f"(d[0]), "+f"(d[1]), "+f"(d[2]), "+f"(d[3])
        : "r"(a[0]), "r"(a[1]), "r"(a[2]), "r"(a[3]), "r"(b[0]), "r"(b[1]));
}
__device__ __forceinline__ float silu_f(float x) {
    return x / (1.f + __expf(-x));
}

// ======================== HMMA GEMM ========================
// 128x128x32 tiles, 8 warps (4m x 2n), warp tile 32x64.
// 4-stage cp.async ring, lookahead 2, ONE barrier per chunk:
// max warp skew = 1 iter; reads {c, c+1}%4, writes (c+3)%4 — disjoint.
#define ROWB 80
#define ARR_B (128*ROWB)
#define STG_B (2*ARR_B)              // 20480 B per stage
#define NSTAGE 4
#define DSMEM_SZ (NSTAGE*STG_B + 1024)   // 82944

template<int EPI>
__global__ __launch_bounds__(256, 2) void tc_gemm(
    const __half* __restrict__ A, const __half* __restrict__ Bw,
    const float* __restrict__ bias, const float* __restrict__ resid,
    float* __restrict__ C, __half* __restrict__ Ch,
    int M, int N, int Kd)
{
    extern __shared__ __align__(1024) char dsm_raw[];
    const int tid = threadIdx.x;
    const int wid = tid >> 5, lane = tid & 31;
    const int row0 = blockIdx.y * 128;
    const int col0 = blockIdx.x * 128;
    const int NC = Kd >> 5;

    uint32_t sbase = smem_u32(dsm_raw);
    sbase = (sbase + 1023) & ~1023u;

    const int wm0 = (wid >> 1) * 32;
    const int wn0 = (wid & 1) * 64;

    float acc[2][8][4];
    #pragma unroll
    for (int i = 0; i < 2; i++)
        #pragma unroll
        for (int j = 0; j < 8; j++)
            #pragma unroll
            for (int r = 0; r < 4; r++) acc[i][j][r] = 0.f;

    auto load_chunk = [&](int c) {
        const int kb = c << 5;
        const uint32_t sb = sbase + (c % NSTAGE) * STG_B;
        #pragma unroll
        for (int arr = 0; arr < 2; arr++) {
            const __half* src = (arr == 0) ? A : Bw;
            const int rb = (arr == 0) ? row0 : col0;
            #pragma unroll
            for (int i2 = 0; i2 < 2; i2++) {
                int idx = tid + i2 * 256;
                int row = idx >> 2, seg = idx & 3;
                cp16(sb + arr * ARR_B + row * ROWB + seg * 16,
                     src + (size_t)(rb + row) * Kd + kb + seg * 8);
            }
        }
        cp_commit();
    };

    load_chunk(0);
    load_chunk(1);

    const int sub = lane >> 3, r8 = lane & 7;

    for (int c = 0; c < NC; c++) {
        if (c + 2 < NC) { load_chunk(c + 2); cp_wait<2>(); }
        else if (c + 1 < NC) cp_wait<1>();
        else cp_wait<0>();
        __syncthreads();   // single barrier per chunk

        const uint32_t sb = sbase + (c % NSTAGE) * STG_B;
        #pragma unroll
        for (int kk = 0; kk < 2; kk++) {
            const int kbyte = kk * 32;
            uint32_t af[2][4];
            #pragma unroll
            for (int mi = 0; mi < 2; mi++) {
                int row = wm0 + mi * 16 + (sub & 1) * 8 + r8;
                uint32_t off = row * ROWB + kbyte + (sub >> 1) * 16;
                ldsm4(af[mi][0], af[mi][1], af[mi][2], af[mi][3], sb + off);
            }
            uint32_t bf[8][2];
            #pragma unroll
            for (int nj = 0; nj < 4; nj++) {
                int row = wn0 + nj * 16 + (sub >> 1) * 8 + r8;
                uint32_t off = row * ROWB + kbyte + (sub & 1) * 16;
                ldsm4(bf[nj*2][0], bf[nj*2][1], bf[nj*2+1][0], bf[nj*2+1][1], sb + ARR_B + off);
            }
            #pragma unroll
            for (int mi = 0; mi < 2; mi++)
                #pragma unroll
                for (int ni = 0; ni < 8; ni++)
                    mma16816(acc[mi][ni], af[mi], bf[ni]);
        }
        // no trailing barrier (4-stage ring keeps writer/reader stages disjoint)
    }

    const int bcol0 = col0 + wn0;
    float2 bv[8];
    if (EPI == 2 || EPI == 3) {
        #pragma unroll
        for (int ni = 0; ni < 8; ni++)
            bv[ni] = *(const float2*)(bias + bcol0 + ni * 8 + (lane & 3) * 2);
    }
    #pragma unroll
    for (int mi = 0; mi < 2; mi++) {
        #pragma unroll
        for (int hf = 0; hf < 2; hf++) {
            const int row = row0 + wm0 + mi * 16 + hf * 8 + (lane >> 2);
            #pragma unroll
            for (int ni = 0; ni < 8; ni++) {
                const int col = bcol0 + ni * 8 + (lane & 3) * 2;
                float y0 = acc[mi][ni][hf*2];
                float y1 = acc[mi][ni][hf*2+1];
                if (EPI == 2 || EPI == 3) { y0 += bv[ni].x; y1 += bv[ni].y; }
                if (EPI == 2) {
                    y0 = 0.5f*y0*(1.f + erff(y0*0.70710678118f));
                    y1 = 0.5f*y1*(1.f + erff(y1*0.70710678118f));
                }
                if (EPI == 1 || EPI == 3) {
                    float2 rv = *(const float2*)(resid + (size_t)row * N + col);
                    y0 += rv.x; y1 += rv.y;
                }
                if (EPI == 2) {
                    __half2 hh(__float2half_rn(y0), __float2half_rn(y1));
                    *(uint32_t*)(Ch + (size_t)row * N + col) = *(uint32_t*)&hh;
                } else {
                    *(float2*)(C + (size_t)row * N + col) = make_float2(y0, y1);
                }
            }
        }
    }
}

// ---------------- LayerNorm -> fp16 ----------------
__global__ __launch_bounds__(256) void ln_kernel(const float* __restrict__ x,
    const float* __restrict__ w, const float* __restrict__ bb,
    __half* __restrict__ oh)
{
    __shared__ float rs[8], rs2[8];
    int row = blockIdx.x, tid = threadIdx.x;
    const float4* xr = (const float4*)(x + (size_t)row * D_);
    float4 v = xr[tid];
    float s  = v.x + v.y + v.z + v.w;
    float s2 = v.x*v.x + v.y*v.y + v.z*v.z + v.w*v.w;
    #pragma unroll
    for (int m = 16; m; m >>= 1) {
        s  += __shfl_xor_sync(~0u, s,  m);
        s2 += __shfl_xor_sync(~0u, s2, m);
    }
    if ((tid & 31) == 0) { rs[tid>>5] = s; rs2[tid>>5] = s2; }
    __syncthreads();
    s = 0.f; s2 = 0.f;
    #pragma unroll
    for (int i = 0; i < 8; i++) { s += rs[i]; s2 += rs2[i]; }
    float mean = s * (1.0f/D_);
    float var  = s2 * (1.0f/D_) - mean*mean;
    float inv  = rsqrtf(var + 1e-5f);
    float4 wv = ((const float4*)w)[tid];
    float4 bv = ((const float4*)bb)[tid];
    float o0 = (v.x-mean)*inv*wv.x + bv.x;
    float o1 = (v.y-mean)*inv*wv.y + bv.y;
    float o2 = (v.z-mean)*inv*wv.z + bv.z;
    float o3 = (v.w-mean)*inv*wv.w + bv.w;
    __half2 h0(__float2half_rn(o0), __float2half_rn(o1));
    __half2 h1(__float2half_rn(o2), __float2half_rn(o3));
    ((uint2*)(oh + (size_t)row * D_))[tid] = make_uint2(*(uint32_t*)&h0, *(uint32_t*)&h1);
}

// ---------------- weight transpose ----------------
__global__ __launch_bounds__(256) void wconvT(const float* __restrict__ W,
    __half* __restrict__ WT, int Kd, int N)
{
    __shared__ float t[32][33];
    int n0 = blockIdx.x * 32, k0 = blockIdx.y * 32;
    int tx = threadIdx.x & 31, ty = threadIdx.x >> 5;
    #pragma unroll
    for (int i = 0; i < 4; i++)
        t[ty + 8*i][tx] = W[(size_t)(k0 + ty + 8*i) * N + n0 + tx];
    __syncthreads();
    #pragma unroll
    for (int i = 0; i < 4; i++)
        WT[(size_t)(n0 + ty + 8*i) * Kd + k0 + tx] = __float2half_rn(t[tx][ty + 8*i]);
}

__global__ __launch_bounds__(256) void wconvT3(const float* __restrict__ Wq,
    const float* __restrict__ Wk, const float* __restrict__ Wv,
    __half* __restrict__ WT)
{
    __shared__ float t[32][33];
    const float* W = (blockIdx.z == 0) ? Wq : (blockIdx.z == 1) ? Wk : Wv;
    __half* dst = WT + (size_t)blockIdx.z * 1024 * 1024;
    int n0 = blockIdx.x * 32, k0 = blockIdx.y * 32;
    int tx = threadIdx.x & 31, ty = threadIdx.x >> 5;
    #pragma unroll
    for (int i = 0; i < 4; i++)
        t[ty + 8*i][tx] = W[(size_t)(k0 + ty + 8*i) * 1024 + n0 + tx];
    __syncthreads();
    #pragma unroll
    for (int i = 0; i < 4; i++)
        dst[(size_t)(n0 + ty + 8*i) * 1024 + k0 + tx] = __float2half_rn(t[tx][ty + 8*i]);
}

// ---------------- alpha/beta -> transposed [B*H, T] ----------------
__global__ __launch_bounds__(128) void ab_kernel(const __half* __restrict__ n,
    const float* __restrict__ Wb, const float* __restrict__ Wa,
    float* __restrict__ alT, float* __restrict__ beT)
{
    int row = blockIdx.x, tid = threadIdx.x;     // row = b*T + t
    int g = tid >> 3, l = tid & 7;
    const float* W = (g < 8) ? Wb : Wa;
    int c = g & 7;
    const __half* nr = n + (size_t)row * D_;
    float s = 0.f;
    for (int d = l; d < D_; d += 8) s = fmaf(__half2float(nr[d]), W[d*H_ + c], s);
    s += __shfl_xor_sync(~0u, s, 1);
    s += __shfl_xor_sync(~0u, s, 2);
    s += __shfl_xor_sync(~0u, s, 4);
    if (l == 0) {
        float sig = 1.f/(1.f + __expf(-s));
        int b = row >> 12, t = row & (T_ - 1);
        size_t oidx = ((size_t)(b * H_ + c)) * T_ + t;
        if (g < 8) beT[oidx] = sig;
        else       alT[oidx] = sig;
    }
}

// ---------------- silu + l2norm on q,k; silu on v -> fp16 ----------------
__global__ __launch_bounds__(128) void act_qkv_kernel(const float* __restrict__ qkv,
    __half* __restrict__ q, __half* __restrict__ kk, __half* __restrict__ v)
{
    __shared__ float rq[4], rk[4];
    int row = blockIdx.x, tid = threadIdx.x;
    int m = row >> 3, h = row & 7;
    const float* src = qkv + (size_t)m * 3072 + h * 128;
    float xq = src[tid], xk = src[1024 + tid], xv = src[2048 + tid];
    float yq = silu_f(xq);
    float yk = silu_f(xk);
    float sq = yq*yq, sk2 = yk*yk;
    #pragma unroll
    for (int mm = 16; mm; mm >>= 1) {
        sq  += __shfl_xor_sync(~0u, sq,  mm);
        sk2 += __shfl_xor_sync(~0u, sk2, mm);
    }
    if ((tid & 31) == 0) { rq[tid>>5] = sq; rk[tid>>5] = sk2; }
    __syncthreads();
    float nq = rq[0]+rq[1]+rq[2]+rq[3];
    float nk = rk[0]+rk[1]+rk[2]+rk[3];
    size_t idx = (size_t)row*128 + tid;
    q[idx]  = __float2half(yq * rsqrtf(nq + 1e-6f));
    kk[idx] = __float2half(yk * rsqrtf(nk + 1e-6f));
    v[idx]  = __float2half(silu_f(xv));
}

// ---------------- gated delta-rule recurrence (chunked smem staging) ----------
__global__ __launch_bounds__(128) void recur_kernel(
    const __half* __restrict__ q, const __half* __restrict__ k, const __half* __restrict__ v,
    const float* __restrict__ alT, const float* __restrict__ beT, __half* __restrict__ o)
{
    __shared__ __align__(16) __half sk[2][NTC*128];
    __shared__ __align__(16) __half sq[2][NTC*128];
    __shared__ __align__(16) __half sv[2][NTC*16];
    __shared__ __align__(16) float sa[2][NTC];
    __shared__ __align__(16) float sb_[2][NTC];

    const int blk = blockIdx.x;
    const int bh = blk >> 3, split = blk & 7;
    const int b = bh >> 3, h = bh & 7;
    const int tid = threadIdx.x;
    const int col = tid >> 3, r8 = tid & 7;
    const size_t base = ((size_t)b * T_ * H_ + h) * (size_t)K_;
    const size_t abbase = (size_t)bh * T_;

    auto load_chunk = [&](int c, int d) {
        const char* kc = (const char*)(k + base + (size_t)c * NTC * (H_*K_));
        const char* qc = (const char*)(q + base + (size_t)c * NTC * (H_*K_));
        const char* vc = (const char*)(v + base + (size_t)c * NTC * (H_*K_) + split*16);
        uint32_t skb = smem_u32(&sk[d][0]);
        uint32_t sqb = smem_u32(&sq[d][0]);
        #pragma unroll
        for (int i = 0; i < 4; i++) {
            int idx = tid + i * 128;
            int row = idx >> 4, seg = idx & 15;
            cp16(skb + row*256 + seg*16, kc + (size_t)row*2048 + seg*16);
            cp16(sqb + row*256 + seg*16, qc + (size_t)row*2048 + seg*16);
        }
        if (tid < 64) {
            int row = tid >> 1, seg = tid & 1;
            cp16(smem_u32(&sv[d][0]) + row*32 + seg*16, vc + (size_t)row*2048 + seg*16);
        } else if (tid < 72) {
            int s = tid - 64;
            cp16(smem_u32(&sa[d][0]) + s*16, (const char*)(alT + abbase + c*NTC) + s*16);
        } else if (tid < 80) {
            int s = tid - 72;
            cp16(smem_u32(&sb_[d][0]) + s*16, (const char*)(beT + abbase + c*NTC) + s*16);
        }
        cp_commit();
    };

    float S[16];
    #pragma unroll
    for (int i = 0; i < 16; i++) S[i] = 0.f;

    const int NCH = T_ / NTC;   // 128
    load_chunk(0, 0);

    for (int c = 0; c < NCH; c++) {
        const int d = c & 1;
        if (c + 1 < NCH) { load_chunk(c + 1, d ^ 1); cp_wait<1>(); }
        else cp_wait<0>();
        __syncthreads();

        const char* skd = (const char*)&sk[d][0] + r8 * 32;
        const char* sqd = (const char*)&sq[d][0] + r8 * 32;

        #pragma unroll 2
        for (int tt = 0; tt < NTC; tt++) {
            // hoist scalar smem reads so LDS latency hides under the shfl chain
            float a  = sa[d][tt], bt = sb_[d][tt];
            float vv = __half2float(sv[d][tt*16 + col]);

            uint4 k0 = *(const uint4*)(skd + tt*256);
            uint4 k1 = *(const uint4*)(skd + tt*256 + 16);
            float kreg[16];
            {
                const __half2* hp0 = (const __half2*)&k0;
                const __half2* hp1 = (const __half2*)&k1;
                #pragma unroll
                for (int j = 0; j < 4; j++) {
                    float2 f0 = __half22float2(hp0[j]);
                    float2 f1 = __half22float2(hp1[j]);
                    kreg[2*j]   = f0.x; kreg[2*j+1]   = f0.y;
                    kreg[8+2*j] = f1.x; kreg[8+2*j+1] = f1.y;
                }
            }
            float kv0 = 0.f, kv1 = 0.f, kv2 = 0.f, kv3 = 0.f;
            #pragma unroll
            for (int i = 0; i < 4; i++) {
                kv0 = fmaf(kreg[4*i+0], S[4*i+0], kv0);
                kv1 = fmaf(kreg[4*i+1], S[4*i+1], kv1);
                kv2 = fmaf(kreg[4*i+2], S[4*i+2], kv2);
                kv3 = fmaf(kreg[4*i+3], S[4*i+3], kv3);
            }
            float kv = (kv0+kv1)+(kv2+kv3);
            kv += __shfl_xor_sync(~0u, kv, 1);
            kv += __shfl_xor_sync(~0u, kv, 2);
            kv += __shfl_xor_sync(~0u, kv, 4);

            float w  = bt * (vv - a * kv);
            #pragma unroll
            for (int i = 0; i < 16; i++) S[i] = fmaf(a, S[i], kreg[i]*w);

            uint4 q0 = *(const uint4*)(sqd + tt*256);
            uint4 q1 = *(const uint4*)(sqd + tt*256 + 16);
            float o0 = 0.f, o1 = 0.f, o2 = 0.f, o3 = 0.f;
            {
                const __half2* hp0 = (const __half2*)&q0;
                const __half2* hp1 = (const __half2*)&q1;
                #pragma unroll
                for (int j = 0; j < 4; j++) {
                    float2 f0 = __half22float2(hp0[j]);
                    float2 f1 = __half22float2(hp1[j]);
                    o0 = fmaf(f0.x, S[2*j],     o0);
                    o1 = fmaf(f0.y, S[2*j+1],   o1);
                    o2 = fmaf(f1.x, S[8+2*j],   o2);
                    o3 = fmaf(f1.y, S[8+2*j+1], o3);
                }
            }
            float oa = (o0+o1)+(o2+o3);
            oa += __shfl_xor_sync(~0u, oa, 1);
            oa += __shfl_xor_sync(~0u, oa, 2);
            oa += __shfl_xor_sync(~0u, oa, 4);
            if (r8 == 0)
                o[base + (size_t)(c*NTC + tt)*(H_*K_) + split*16 + col] = __float2half(oa);
        }
        __syncthreads();
    }
}

// ---------------- launch ----------------
extern "C" void kernel_launch(void* const* d_in, const int* in_sizes, int n_in,
                              void* d_out, int out_size)
{
    const float* x    = (const float*)d_in[0];
    const float* Wq   = (const float*)d_in[1];
    const float* Wk   = (const float*)d_in[2];
    const float* Wv   = (const float*)d_in[3];
    const float* Wb   = (const float*)d_in[4];
    const float* Wa   = (const float*)d_in[5];
    const float* Wo   = (const float*)d_in[6];
    const float* ln1w = (const float*)d_in[7];
    const float* ln1b = (const float*)d_in[8];
    const float* ln2w = (const float*)d_in[9];
    const float* ln2b = (const float*)d_in[10];
    const float* W1   = (const float*)d_in[11];
    const float* b1   = (const float*)d_in[12];
    const float* W2   = (const float*)d_in[13];
    const float* b2   = (const float*)d_in[14];
    float* out = (float*)d_out;

    float *qkv_, *al_, *be_, *x1_;
    __half *nh, *qh, *kh, *vh, *oh, *hh, *fh, *wqkv, *wo, *w1, *w2;
    cudaGetSymbolAddress((void**)&nh,   g_nh);
    cudaGetSymbolAddress((void**)&qkv_, g_qkv);
    cudaGetSymbolAddress((void**)&qh,   g_qh);
    cudaGetSymbolAddress((void**)&kh,   g_kh);
    cudaGetSymbolAddress((void**)&vh,   g_vh);
    cudaGetSymbolAddress((void**)&al_,  g_al);
    cudaGetSymbolAddress((void**)&be_,  g_be);
    cudaGetSymbolAddress((void**)&oh,   g_oh);
    cudaGetSymbolAddress((void**)&x1_,  g_x1);
    cudaGetSymbolAddress((void**)&hh,   g_hh);
    cudaGetSymbolAddress((void**)&fh,   g_fh);
    cudaGetSymbolAddress((void**)&wqkv, g_wqkv);
    cudaGetSymbolAddress((void**)&wo,   g_wo);
    cudaGetSymbolAddress((void**)&w1,   g_w1);
    cudaGetSymbolAddress((void**)&w2,   g_w2);

    cudaFuncSetAttribute(tc_gemm<0>, cudaFuncAttributeMaxDynamicSharedMemorySize, DSMEM_SZ);
    cudaFuncSetAttribute(tc_gemm<1>, cudaFuncAttributeMaxDynamicSharedMemorySize, DSMEM_SZ);
    cudaFuncSetAttribute(tc_gemm<2>, cudaFuncAttributeMaxDynamicSharedMemorySize, DSMEM_SZ);
    cudaFuncSetAttribute(tc_gemm<3>, cudaFuncAttributeMaxDynamicSharedMemorySize, DSMEM_SZ);

    ln_kernel<<<M_, 256>>>(x, ln1w, ln1b, nh);                               // 0
    wconvT3<<<dim3(32, 32, 3), 256>>>(Wq, Wk, Wv, wqkv);                     // 1
    ab_kernel<<<M_, 128>>>(nh, Wb, Wa, al_, be_);                            // 2

    dim3 gqkv(3072/128, M_/128);
    tc_gemm<0><<<gqkv, 256, DSMEM_SZ>>>(nh, wqkv, nullptr, nullptr, qkv_, nullptr, M_, 3072, 1024); // 3 <- PROFILED

    act_qkv_kernel<<<M_*H_, 128>>>(qkv_, qh, kh, vh);                        // 4

    recur_kernel<<<B_*H_*8, 128>>>(qh, kh, vh, al_, be_, oh);                // 5

    wconvT<<<dim3(1024/32, 1024/32), 256>>>(Wo, wo, 1024, 1024);             // 6

    dim3 g1(1024/128, M_/128);
    tc_gemm<1><<<g1, 256, DSMEM_SZ>>>(oh, wo, nullptr, x, x1_, nullptr, M_, 1024, 1024); // 7

    ln_kernel<<<M_, 256>>>(x1_, ln2w, ln2b, hh);                             // 8

    wconvT<<<dim3(4096/32, 1024/32), 256>>>(W1, w1, 1024, 4096);             // 9
    wconvT<<<dim3(1024/32, 4096/32), 256>>>(W2, w2, 4096, 1024);             // 10

    dim3 g2(4096/128, M_/128);
    tc_gemm<2><<<g2, 256, DSMEM_SZ>>>(hh, w1, b1, nullptr, nullptr, fh, M_, 4096, 1024); // 11
    tc_gemm<3><<<g1, 256, DSMEM_SZ>>>(fh, w2, b2, x1_, out, nullptr, M_, 1024, 4096);    // 12
}